// round 3
// baseline (speedup 1.0000x reference)
#include <cuda_runtime.h>
#include <cstdint>

// ---------------- constants ----------------
#define BATCH   256
#define TSTEPS  600
#define HID     512
#define EMBED   50
#define VOCAB   83
#define MROWS   (TSTEPS*BATCH)      // 153600
#define GATE3   (3*HID)             // 1536
#define INDEC   (6*EMBED)           // 300

// ---------------- scratch (__device__ globals; no allocation allowed) ----------------
__device__ float g_ha[BATCH*HID];        // hidden@W_hp + b_hp + b_ep
__device__ float g_scores[BATCH*TSTEPS]; // pre-softmax scores [b*600+t]
__device__ float g_ctx[BATCH*HID];       // attention context
__device__ float g_indec[BATCH*INDEC];   // [embed(50) | context@W_cs (250)]
__device__ float g_gi[BATCH*GATE3];
__device__ float g_gh[BATCH*GATE3];

// ---------------- MUFU-free fast math ----------------
// exp2(u) for u in [-30,30]: split u = n + f, poly for 2^f, splice exponent bits.
__device__ __forceinline__ float fexp2_nomufu(float u) {
    float k = u + 12582912.0f;                       // round-to-nearest int
    int   n = __float_as_int(k) - 0x4B400000;        // integer part
    float f = u - (k - 12582912.0f);                 // f in [-0.5, 0.5]
    float p = 0.0013333558f;
    p = fmaf(p, f, 0.0096181291f);
    p = fmaf(p, f, 0.0555041087f);
    p = fmaf(p, f, 0.2402265069f);
    p = fmaf(p, f, 0.6931471806f);
    p = fmaf(p, f, 1.0f);
    return __int_as_float(__float_as_int(p) + (n << 23));
}

// tanh(x) = 1 - 2/(exp(2x)+1), reciprocal via magic + 3 Newton steps (no MUFU).
__device__ __forceinline__ float fast_tanh(float x) {
    float u = fminf(fmaxf(x * 2.8853900818f, -30.0f), 30.0f);  // 2x*log2(e)
    float e = fexp2_nomufu(u);                                  // exp(2x)
    float d = e + 1.0f;
    float y = __int_as_float(0x7EF311C3 - __float_as_int(d));   // ~1/d guess
    y = y * fmaf(-d, y, 2.0f);
    y = y * fmaf(-d, y, 2.0f);
    y = y * fmaf(-d, y, 2.0f);
    return fmaf(-2.0f, y, 1.0f);
}

__device__ __forceinline__ float fast_sigmoid(float x) {
    return fmaf(0.5f, fast_tanh(0.5f * x), 0.5f);
}

// ---------------- generic small GEMM: C[256,N] = A[256,K] @ W[K,N] + b1 (+ b2) ----------------
// grid (N/128, 256/16), 128 threads. 16 rows per block cached in smem.
__global__ void gemm16(const float* __restrict__ A, const float* __restrict__ W,
                       const float* __restrict__ b1, const float* __restrict__ b2,
                       float* __restrict__ C, int K, int N)
{
    __shared__ float hs[16][HID];
    const int n  = blockIdx.x * 128 + threadIdx.x;
    const int b0 = blockIdx.y * 16;

    for (int idx = threadIdx.x; idx < 16 * K; idx += 128) {
        int r = idx / K, c = idx - r * K;
        hs[r][c] = A[(b0 + r) * K + c];
    }
    __syncthreads();

    float acc[16];
#pragma unroll
    for (int r = 0; r < 16; ++r) acc[r] = 0.0f;

    for (int k = 0; k < K; k += 4) {
        float w0 = W[(k + 0) * N + n];
        float w1 = W[(k + 1) * N + n];
        float w2 = W[(k + 2) * N + n];
        float w3 = W[(k + 3) * N + n];
#pragma unroll
        for (int r = 0; r < 16; ++r) {
            float4 h4 = *(const float4*)&hs[r][k];
            acc[r] = fmaf(h4.x, w0, acc[r]);
            acc[r] = fmaf(h4.y, w1, acc[r]);
            acc[r] = fmaf(h4.z, w2, acc[r]);
            acc[r] = fmaf(h4.w, w3, acc[r]);
        }
    }
    float bias = b1[n] + (b2 ? b2[n] : 0.0f);
#pragma unroll
    for (int r = 0; r < 16; ++r)
        C[(b0 + r) * N + n] = acc[r] + bias;
}

// ---------------- big fused kernel: scores[b,t] = w_v . tanh(enc_row @ W_ep + ha[b,:]) ----------------
// 128x128x16 tiling, 8x8 microtiles, 256 threads, epilogue reduces N entirely.
__global__ __launch_bounds__(256, 2)
void attn_scores_kernel(const float* __restrict__ enc,
                        const float* __restrict__ Wep,
                        const float* __restrict__ wv,
                        float* __restrict__ scores)
{
    __shared__ float As[16][132];   // transposed A tile, padded
    __shared__ float Bs[16][128];
    __shared__ float rowScore[128];

    const int tid = threadIdx.x;
    const int tx  = tid & 15;
    const int ty  = tid >> 4;
    const int m0  = blockIdx.x * 128;

    const int arow = tid >> 2;            // 0..63
    const int akq  = (tid & 3) * 4;       // k offset 0/4/8/12
    const int bkr  = tid >> 5;            // 0..7
    const int bcq  = (tid & 31) * 4;      // col offset

    if (tid < 128) rowScore[tid] = 0.0f;

    const float* Aptr0 = enc + (m0 + arow) * HID + akq;
    const float* Aptr1 = Aptr0 + 64 * HID;

    for (int nc = 0; nc < 4; ++nc) {
        const int n0 = nc * 128;
        float acc[8][8];
#pragma unroll
        for (int r = 0; r < 8; ++r)
#pragma unroll
            for (int c = 0; c < 8; ++c) acc[r][c] = 0.0f;

        float4 a0 = *(const float4*)(Aptr0);
        float4 a1 = *(const float4*)(Aptr1);
        float4 b0 = *(const float4*)(Wep + bkr * HID + n0 + bcq);
        float4 b1 = *(const float4*)(Wep + (bkr + 8) * HID + n0 + bcq);

        for (int k0 = 0; k0 < HID; k0 += 16) {
            __syncthreads();
            As[akq + 0][arow]      = a0.x;
            As[akq + 1][arow]      = a0.y;
            As[akq + 2][arow]      = a0.z;
            As[akq + 3][arow]      = a0.w;
            As[akq + 0][arow + 64] = a1.x;
            As[akq + 1][arow + 64] = a1.y;
            As[akq + 2][arow + 64] = a1.z;
            As[akq + 3][arow + 64] = a1.w;
            *(float4*)&Bs[bkr][bcq]     = b0;
            *(float4*)&Bs[bkr + 8][bcq] = b1;
            __syncthreads();

            if (k0 + 16 < HID) {   // prefetch next tile
                a0 = *(const float4*)(Aptr0 + k0 + 16);
                a1 = *(const float4*)(Aptr1 + k0 + 16);
                b0 = *(const float4*)(Wep + (k0 + 16 + bkr) * HID + n0 + bcq);
                b1 = *(const float4*)(Wep + (k0 + 16 + bkr + 8) * HID + n0 + bcq);
            }

#pragma unroll
            for (int kk = 0; kk < 16; ++kk) {
                float4 x0 = *(const float4*)&As[kk][ty * 8];
                float4 x1 = *(const float4*)&As[kk][ty * 8 + 4];
                float4 y0 = *(const float4*)&Bs[kk][tx * 8];
                float4 y1 = *(const float4*)&Bs[kk][tx * 8 + 4];
                float ar[8] = {x0.x, x0.y, x0.z, x0.w, x1.x, x1.y, x1.z, x1.w};
                float br[8] = {y0.x, y0.y, y0.z, y0.w, y1.x, y1.y, y1.z, y1.w};
#pragma unroll
                for (int r = 0; r < 8; ++r)
#pragma unroll
                    for (int c = 0; c < 8; ++c)
                        acc[r][c] = fmaf(ar[r], br[c], acc[r][c]);
            }
        }

        // fused epilogue: + ha  -> tanh -> * w_v -> reduce over the 128 cols of this chunk
        float wv8[8];
#pragma unroll
        for (int j = 0; j < 8; ++j) wv8[j] = wv[n0 + tx * 8 + j];
#pragma unroll
        for (int r = 0; r < 8; ++r) {
            const int m  = m0 + ty * 8 + r;
            const int bb = m & 255;                 // b = m % BATCH
            const float* hap = g_ha + bb * HID + n0 + tx * 8;
            float4 h0 = *(const float4*)hap;
            float4 h1 = *(const float4*)(hap + 4);
            float p;
            p  = wv8[0] * fast_tanh(acc[r][0] + h0.x);
            p += wv8[1] * fast_tanh(acc[r][1] + h0.y);
            p += wv8[2] * fast_tanh(acc[r][2] + h0.z);
            p += wv8[3] * fast_tanh(acc[r][3] + h0.w);
            p += wv8[4] * fast_tanh(acc[r][4] + h1.x);
            p += wv8[5] * fast_tanh(acc[r][5] + h1.y);
            p += wv8[6] * fast_tanh(acc[r][6] + h1.z);
            p += wv8[7] * fast_tanh(acc[r][7] + h1.w);
            p += __shfl_xor_sync(0xffffffffu, p, 8);
            p += __shfl_xor_sync(0xffffffffu, p, 4);
            p += __shfl_xor_sync(0xffffffffu, p, 2);
            p += __shfl_xor_sync(0xffffffffu, p, 1);
            if (tx == 0) rowScore[ty * 8 + r] += p;   // same owner thread every chunk
        }
    }
    __syncthreads();
    if (tid < 128) {
        const int m = m0 + tid;
        scores[(m & 255) * TSTEPS + (m >> 8)] = rowScore[tid];   // [b*600 + t]
    }
}

// ---------------- softmax over T per batch row ----------------
__global__ void softmax_T(const float* __restrict__ scores, float* __restrict__ attn)
{
    __shared__ float red[256];
    const int b = blockIdx.x, tid = threadIdx.x;
    const float* s = scores + b * TSTEPS;

    float mx = -1e30f;
    for (int t = tid; t < TSTEPS; t += 256) mx = fmaxf(mx, s[t]);
    red[tid] = mx; __syncthreads();
    for (int o = 128; o; o >>= 1) { if (tid < o) red[tid] = fmaxf(red[tid], red[tid + o]); __syncthreads(); }
    mx = red[0]; __syncthreads();

    float sum = 0.0f;
    for (int t = tid; t < TSTEPS; t += 256) sum += __expf(s[t] - mx);
    red[tid] = sum; __syncthreads();
    for (int o = 128; o; o >>= 1) { if (tid < o) red[tid] += red[tid + o]; __syncthreads(); }
    const float inv = 1.0f / red[0];

    for (int t = tid; t < TSTEPS; t += 256)
        attn[b * TSTEPS + t] = __expf(s[t] - mx) * inv;
}

// ---------------- context[b,h] = sum_t attn[b,t] * enc[t,b,h] ----------------
__global__ void context_kernel(const float* __restrict__ enc,
                               const float* __restrict__ attn,
                               float* __restrict__ ctx)
{
    __shared__ float aw[TSTEPS];
    const int b = blockIdx.y;
    const int h = blockIdx.x * 128 + threadIdx.x;
    for (int t = threadIdx.x; t < TSTEPS; t += 128) aw[t] = attn[b * TSTEPS + t];
    __syncthreads();

    const float* base = enc + b * HID + h;
    float acc[8];
#pragma unroll
    for (int u = 0; u < 8; ++u) acc[u] = 0.0f;
    for (int t = 0; t < TSTEPS; t += 8) {
#pragma unroll
        for (int u = 0; u < 8; ++u)
            acc[u] = fmaf(aw[t + u], base[(t + u) * (BATCH * HID)], acc[u]);
    }
    float s = ((acc[0] + acc[1]) + (acc[2] + acc[3])) + ((acc[4] + acc[5]) + (acc[6] + acc[7]));
    ctx[b * HID + h] = s;
}

// ---------------- argmax-embed + context@W_cs -> in_dec[b, 300] ----------------
__global__ void indec_kernel(const float* __restrict__ in_char,
                             const float* __restrict__ emb,
                             const float* __restrict__ Wcs,
                             const float* __restrict__ bcs)
{
    __shared__ float ctx_s[HID];
    __shared__ int   top_s;
    const int b = blockIdx.x, tid = threadIdx.x;

    for (int i = tid; i < HID; i += 256) ctx_s[i] = g_ctx[b * HID + i];

    if (tid < 32) {
        float bv = -1e30f; int bi = 0;
        for (int i = tid; i < VOCAB; i += 32) {
            float v = in_char[b * VOCAB + i];
            if (v > bv) { bv = v; bi = i; }
        }
        for (int o = 16; o; o >>= 1) {
            float ov = __shfl_xor_sync(0xffffffffu, bv, o);
            int   oi = __shfl_xor_sync(0xffffffffu, bi, o);
            if (ov > bv || (ov == bv && oi < bi)) { bv = ov; bi = oi; }
        }
        if (tid == 0) top_s = bi;
    }
    __syncthreads();

    if (tid < EMBED) g_indec[b * INDEC + tid] = emb[top_s * EMBED + tid];

    if (tid < 250) {
        float acc = bcs[tid];
        for (int k = 0; k < HID; k += 4) {
            float4 c4 = *(const float4*)&ctx_s[k];
            acc = fmaf(c4.x, Wcs[(k + 0) * 250 + tid], acc);
            acc = fmaf(c4.y, Wcs[(k + 1) * 250 + tid], acc);
            acc = fmaf(c4.z, Wcs[(k + 2) * 250 + tid], acc);
            acc = fmaf(c4.w, Wcs[(k + 3) * 250 + tid], acc);
        }
        g_indec[b * INDEC + EMBED + tid] = acc;
    }
}

// ---------------- GRU gates -> new_h ----------------
__global__ void gru_gates(const float* __restrict__ hidden, float* __restrict__ newh)
{
    const int b = blockIdx.x, n = threadIdx.x;  // 512 threads
    const float* gi = g_gi + b * GATE3;
    const float* gh = g_gh + b * GATE3;
    float r  = fast_sigmoid(gi[n]        + gh[n]);
    float z  = fast_sigmoid(gi[HID + n]  + gh[HID + n]);
    float nn = fast_tanh(gi[2 * HID + n] + r * gh[2 * HID + n]);
    float h  = hidden[b * HID + n];
    newh[b * HID + n] = (1.0f - z) * nn + z * h;
}

// ---------------- output = softmax(new_h @ W_out + b_out) ----------------
__global__ void out_softmax(const float* __restrict__ newh,
                            const float* __restrict__ Wout,
                            const float* __restrict__ bout,
                            float* __restrict__ out)
{
    __shared__ float nh[HID];
    __shared__ float sc[VOCAB];
    __shared__ float red[2];
    const int b = blockIdx.x, tid = threadIdx.x;  // 128 threads

    for (int i = tid; i < HID; i += 128) nh[i] = newh[b * HID + i];
    __syncthreads();

    if (tid < VOCAB) {
        float acc = bout[tid];
        for (int k = 0; k < HID; ++k) acc = fmaf(nh[k], Wout[k * VOCAB + tid], acc);
        sc[tid] = acc;
    }
    __syncthreads();

    if (tid < 32) {
        float mx = -1e30f;
        for (int i = tid; i < VOCAB; i += 32) mx = fmaxf(mx, sc[i]);
        for (int o = 16; o; o >>= 1) mx = fmaxf(mx, __shfl_xor_sync(0xffffffffu, mx, o));
        float sum = 0.0f;
        for (int i = tid; i < VOCAB; i += 32) sum += __expf(sc[i] - mx);
        for (int o = 16; o; o >>= 1) sum += __shfl_xor_sync(0xffffffffu, sum, o);
        if (tid == 0) { red[0] = mx; red[1] = sum; }
    }
    __syncthreads();

    if (tid < VOCAB)
        out[b * VOCAB + tid] = __expf(sc[tid] - red[0]) * (1.0f / red[1]);
}

// ---------------- launch ----------------
extern "C" void kernel_launch(void* const* d_in, const int* in_sizes, int n_in,
                              void* d_out, int out_size)
{
    const float* in_char = (const float*)d_in[0];
    const float* hidden  = (const float*)d_in[1];
    const float* enc     = (const float*)d_in[2];
    const float* W_hp    = (const float*)d_in[3];
    const float* b_hp    = (const float*)d_in[4];
    const float* W_ep    = (const float*)d_in[5];
    const float* b_ep    = (const float*)d_in[6];
    const float* w_v     = (const float*)d_in[7];
    /* d_in[8] = b_v: constant shift under softmax, mathematically irrelevant */
    const float* W_cs    = (const float*)d_in[9];
    const float* b_cs    = (const float*)d_in[10];
    const float* emb     = (const float*)d_in[11];
    const float* W_ih    = (const float*)d_in[12];
    const float* b_ih    = (const float*)d_in[13];
    const float* W_hh    = (const float*)d_in[14];
    const float* b_hh    = (const float*)d_in[15];
    const float* W_out   = (const float*)d_in[16];
    const float* b_out   = (const float*)d_in[17];

    float* out       = (float*)d_out;
    float* out_probs = out;                                  // [256,83]
    float* out_newh  = out + BATCH * VOCAB;                  // [1,256,512]
    float* out_attn  = out + BATCH * VOCAB + BATCH * HID;    // [256,600]

    void *p_ha, *p_scores, *p_ctx, *p_indec, *p_gi, *p_gh;
    cudaGetSymbolAddress(&p_ha,     g_ha);
    cudaGetSymbolAddress(&p_scores, g_scores);
    cudaGetSymbolAddress(&p_ctx,    g_ctx);
    cudaGetSymbolAddress(&p_indec,  g_indec);
    cudaGetSymbolAddress(&p_gi,     g_gi);
    cudaGetSymbolAddress(&p_gh,     g_gh);

    // 1. hidden_attn = hidden @ W_hp + b_hp + b_ep  (b_ep folded in)
    gemm16<<<dim3(HID / 128, BATCH / 16), 128>>>(hidden, W_hp, b_hp, b_ep,
                                                 (float*)p_ha, HID, HID);
    // 2. fused big GEMM + tanh + w_v reduction -> scores
    attn_scores_kernel<<<MROWS / 128, 256>>>(enc, W_ep, w_v, (float*)p_scores);
    // 3. softmax over T -> attention weights (output #3)
    softmax_T<<<BATCH, 256>>>((const float*)p_scores, out_attn);
    // 4. context = attn-weighted sum of encoder
    context_kernel<<<dim3(HID / 128, BATCH), 128>>>(enc, out_attn, (float*)p_ctx);
    // 5. argmax-embed + context@W_cs -> in_dec
    indec_kernel<<<BATCH, 256>>>(in_char, emb, W_cs, b_cs);
    // 6. gi = in_dec @ W_ih + b_ih
    gemm16<<<dim3(GATE3 / 128, BATCH / 16), 128>>>((const float*)p_indec, W_ih, b_ih,
                                                   nullptr, (float*)p_gi, INDEC, GATE3);
    // 7. gh = h @ W_hh + b_hh
    gemm16<<<dim3(GATE3 / 128, BATCH / 16), 128>>>(hidden, W_hh, b_hh,
                                                   nullptr, (float*)p_gh, HID, GATE3);
    // 8. GRU gates -> new_h (output #2)
    gru_gates<<<BATCH, HID>>>(hidden, out_newh);
    // 9. output probabilities (output #1)
    out_softmax<<<BATCH, 128>>>(out_newh, W_out, b_out, out_probs);
}

// round 4
// speedup vs baseline: 1.1043x; 1.1043x over previous
#include <cuda_runtime.h>
#include <cstdint>

// ---------------- constants ----------------
#define BATCH   256
#define TSTEPS  600
#define HID     512
#define EMBED   50
#define VOCAB   83
#define MROWS   (TSTEPS*BATCH)      // 153600
#define GATE3   (3*HID)             // 1536
#define INDEC   (6*EMBED)           // 300

// ---------------- scratch (__device__ globals; no allocation allowed) ----------------
__device__ float g_ha[BATCH*HID];        // hidden@W_hp + b_hp + b_ep
__device__ float g_scores[BATCH*TSTEPS]; // pre-softmax scores [b*600+t]
__device__ float g_ctx[BATCH*HID];       // attention context
__device__ float g_indec[BATCH*INDEC];   // [embed(50) | context@W_cs (250)]
__device__ float g_gi[BATCH*GATE3];
__device__ float g_gh[BATCH*GATE3];

// ---------------- packed f32x2 helpers (Blackwell FFMA2 path) ----------------
__device__ __forceinline__ unsigned long long pk2_dup(float v) {
    unsigned long long r;
    asm("mov.b64 %0, {%1, %1};" : "=l"(r) : "f"(v));
    return r;
}
__device__ __forceinline__ void fma2(unsigned long long &d,
                                     unsigned long long a,
                                     unsigned long long b) {
    asm("fma.rn.f32x2 %0, %1, %2, %0;" : "+l"(d) : "l"(a), "l"(b));
}
__device__ __forceinline__ void upk2(unsigned long long v, float &lo, float &hi) {
    asm("mov.b64 {%0, %1}, %2;" : "=f"(lo), "=f"(hi) : "l"(v));
}

// ---------------- MUFU-free fast math ----------------
__device__ __forceinline__ float fexp2_nomufu(float u) {
    float k = u + 12582912.0f;                       // round-to-nearest int
    int   n = __float_as_int(k) - 0x4B400000;        // integer part
    float f = u - (k - 12582912.0f);                 // f in [-0.5, 0.5]
    float p = 0.0013333558f;
    p = fmaf(p, f, 0.0096181291f);
    p = fmaf(p, f, 0.0555041087f);
    p = fmaf(p, f, 0.2402265069f);
    p = fmaf(p, f, 0.6931471806f);
    p = fmaf(p, f, 1.0f);
    return __int_as_float(__float_as_int(p) + (n << 23));
}

// tanh(x) = 1 - 2/(exp(2x)+1), reciprocal via magic + 3 Newton steps (no MUFU).
__device__ __forceinline__ float fast_tanh(float x) {
    float u = fminf(fmaxf(x * 2.8853900818f, -30.0f), 30.0f);  // 2x*log2(e)
    float e = fexp2_nomufu(u);                                  // exp(2x)
    float d = e + 1.0f;
    float y = __int_as_float(0x7EF311C3 - __float_as_int(d));   // ~1/d guess
    y = y * fmaf(-d, y, 2.0f);
    y = y * fmaf(-d, y, 2.0f);
    y = y * fmaf(-d, y, 2.0f);
    return fmaf(-2.0f, y, 1.0f);
}

__device__ __forceinline__ float fast_sigmoid(float x) {
    return fmaf(0.5f, fast_tanh(0.5f * x), 0.5f);
}

// ---------------- generic small GEMM: C[256,N] = A[256,K] @ W[K,N] + b1 (+ b2) ----------------
__global__ void gemm16(const float* __restrict__ A, const float* __restrict__ W,
                       const float* __restrict__ b1, const float* __restrict__ b2,
                       float* __restrict__ C, int K, int N)
{
    __shared__ float hs[16][HID];
    const int n  = blockIdx.x * 128 + threadIdx.x;
    const int b0 = blockIdx.y * 16;

    for (int idx = threadIdx.x; idx < 16 * K; idx += 128) {
        int r = idx / K, c = idx - r * K;
        hs[r][c] = A[(b0 + r) * K + c];
    }
    __syncthreads();

    float acc[16];
#pragma unroll
    for (int r = 0; r < 16; ++r) acc[r] = 0.0f;

    for (int k = 0; k < K; k += 4) {
        float w0 = W[(k + 0) * N + n];
        float w1 = W[(k + 1) * N + n];
        float w2 = W[(k + 2) * N + n];
        float w3 = W[(k + 3) * N + n];
#pragma unroll
        for (int r = 0; r < 16; ++r) {
            float4 h4 = *(const float4*)&hs[r][k];
            acc[r] = fmaf(h4.x, w0, acc[r]);
            acc[r] = fmaf(h4.y, w1, acc[r]);
            acc[r] = fmaf(h4.z, w2, acc[r]);
            acc[r] = fmaf(h4.w, w3, acc[r]);
        }
    }
    float bias = b1[n] + (b2 ? b2[n] : 0.0f);
#pragma unroll
    for (int r = 0; r < 16; ++r)
        C[(b0 + r) * N + n] = acc[r] + bias;
}

// ---------------- big fused kernel: scores[b,t] = w_v . tanh(enc_row @ W_ep + ha[b,:]) ----------------
// 128x128x16 tiling, 8x8 microtiles accumulated as packed f32x2 column pairs.
__global__ __launch_bounds__(256, 2)
void attn_scores_kernel(const float* __restrict__ enc,
                        const float* __restrict__ Wep,
                        const float* __restrict__ wv,
                        float* __restrict__ scores)
{
    __shared__ float As[16][132];   // transposed A tile, padded
    __shared__ float Bs[16][128];
    __shared__ float rowScore[128];

    const int tid = threadIdx.x;
    const int tx  = tid & 15;
    const int ty  = tid >> 4;
    const int m0  = blockIdx.x * 128;

    const int arow = tid >> 2;            // 0..63
    const int akq  = (tid & 3) * 4;       // k offset 0/4/8/12
    const int bkr  = tid >> 5;            // 0..7
    const int bcq  = (tid & 31) * 4;      // col offset

    if (tid < 128) rowScore[tid] = 0.0f;

    const float* Aptr0 = enc + (m0 + arow) * HID + akq;
    const float* Aptr1 = Aptr0 + 64 * HID;

    for (int nc = 0; nc < 4; ++nc) {
        const int n0 = nc * 128;
        // 8 rows x 4 packed column-pairs (each u64 = cols 2cp, 2cp+1)
        unsigned long long accp[8][4];
#pragma unroll
        for (int r = 0; r < 8; ++r)
#pragma unroll
            for (int cp = 0; cp < 4; ++cp) accp[r][cp] = 0ULL;

        float4 pa0 = *(const float4*)(Aptr0);
        float4 pa1 = *(const float4*)(Aptr1);
        float4 pb0 = *(const float4*)(Wep + bkr * HID + n0 + bcq);
        float4 pb1 = *(const float4*)(Wep + (bkr + 8) * HID + n0 + bcq);

        for (int k0 = 0; k0 < HID; k0 += 16) {
            __syncthreads();
            As[akq + 0][arow]      = pa0.x;
            As[akq + 1][arow]      = pa0.y;
            As[akq + 2][arow]      = pa0.z;
            As[akq + 3][arow]      = pa0.w;
            As[akq + 0][arow + 64] = pa1.x;
            As[akq + 1][arow + 64] = pa1.y;
            As[akq + 2][arow + 64] = pa1.z;
            As[akq + 3][arow + 64] = pa1.w;
            *(float4*)&Bs[bkr][bcq]     = pb0;
            *(float4*)&Bs[bkr + 8][bcq] = pb1;
            __syncthreads();

            if (k0 + 16 < HID) {   // prefetch next tile
                pa0 = *(const float4*)(Aptr0 + k0 + 16);
                pa1 = *(const float4*)(Aptr1 + k0 + 16);
                pb0 = *(const float4*)(Wep + (k0 + 16 + bkr) * HID + n0 + bcq);
                pb1 = *(const float4*)(Wep + (k0 + 16 + bkr + 8) * HID + n0 + bcq);
            }

#pragma unroll
            for (int kk = 0; kk < 16; ++kk) {
                float4 x0 = *(const float4*)&As[kk][ty * 8];
                float4 x1 = *(const float4*)&As[kk][ty * 8 + 4];
                // B pairs straight from shared as 64-bit lanes (no pack needed)
                ulonglong2 yb0 = *(const ulonglong2*)&Bs[kk][tx * 8];
                ulonglong2 yb1 = *(const ulonglong2*)&Bs[kk][tx * 8 + 4];
                unsigned long long b2[4] = {yb0.x, yb0.y, yb1.x, yb1.y};
                float ar[8] = {x0.x, x0.y, x0.z, x0.w, x1.x, x1.y, x1.z, x1.w};
#pragma unroll
                for (int r = 0; r < 8; ++r) {
                    unsigned long long a2 = pk2_dup(ar[r]);   // {a,a}
                    fma2(accp[r][0], a2, b2[0]);
                    fma2(accp[r][1], a2, b2[1]);
                    fma2(accp[r][2], a2, b2[2]);
                    fma2(accp[r][3], a2, b2[3]);
                }
            }
        }

        // fused epilogue: + ha -> tanh -> * w_v -> reduce over this 128-col chunk
        float wv8[8];
#pragma unroll
        for (int j = 0; j < 8; ++j) wv8[j] = wv[n0 + tx * 8 + j];
#pragma unroll
        for (int r = 0; r < 8; ++r) {
            float av[8];
#pragma unroll
            for (int cp = 0; cp < 4; ++cp)
                upk2(accp[r][cp], av[2 * cp], av[2 * cp + 1]);

            const int m  = m0 + ty * 8 + r;
            const int bb = m & 255;                 // b = m % BATCH
            const float* hap = g_ha + bb * HID + n0 + tx * 8;
            float4 h0 = *(const float4*)hap;
            float4 h1 = *(const float4*)(hap + 4);
            float p;
            p  = wv8[0] * fast_tanh(av[0] + h0.x);
            p += wv8[1] * fast_tanh(av[1] + h0.y);
            p += wv8[2] * fast_tanh(av[2] + h0.z);
            p += wv8[3] * fast_tanh(av[3] + h0.w);
            p += wv8[4] * fast_tanh(av[4] + h1.x);
            p += wv8[5] * fast_tanh(av[5] + h1.y);
            p += wv8[6] * fast_tanh(av[6] + h1.z);
            p += wv8[7] * fast_tanh(av[7] + h1.w);
            p += __shfl_xor_sync(0xffffffffu, p, 8);
            p += __shfl_xor_sync(0xffffffffu, p, 4);
            p += __shfl_xor_sync(0xffffffffu, p, 2);
            p += __shfl_xor_sync(0xffffffffu, p, 1);
            if (tx == 0) rowScore[ty * 8 + r] += p;   // same owner thread every chunk
        }
    }
    __syncthreads();
    if (tid < 128) {
        const int m = m0 + tid;
        scores[(m & 255) * TSTEPS + (m >> 8)] = rowScore[tid];   // [b*600 + t]
    }
}

// ---------------- softmax over T per batch row ----------------
__global__ void softmax_T(const float* __restrict__ scores, float* __restrict__ attn)
{
    __shared__ float red[256];
    const int b = blockIdx.x, tid = threadIdx.x;
    const float* s = scores + b * TSTEPS;

    float mx = -1e30f;
    for (int t = tid; t < TSTEPS; t += 256) mx = fmaxf(mx, s[t]);
    red[tid] = mx; __syncthreads();
    for (int o = 128; o; o >>= 1) { if (tid < o) red[tid] = fmaxf(red[tid], red[tid + o]); __syncthreads(); }
    mx = red[0]; __syncthreads();

    float sum = 0.0f;
    for (int t = tid; t < TSTEPS; t += 256) sum += __expf(s[t] - mx);
    red[tid] = sum; __syncthreads();
    for (int o = 128; o; o >>= 1) { if (tid < o) red[tid] += red[tid + o]; __syncthreads(); }
    const float inv = 1.0f / red[0];

    for (int t = tid; t < TSTEPS; t += 256)
        attn[b * TSTEPS + t] = __expf(s[t] - mx) * inv;
}

// ---------------- context[b,h] = sum_t attn[b,t] * enc[t,b,h] ----------------
__global__ void context_kernel(const float* __restrict__ enc,
                               const float* __restrict__ attn,
                               float* __restrict__ ctx)
{
    __shared__ float aw[TSTEPS];
    const int b = blockIdx.y;
    const int h = blockIdx.x * 128 + threadIdx.x;
    for (int t = threadIdx.x; t < TSTEPS; t += 128) aw[t] = attn[b * TSTEPS + t];
    __syncthreads();

    const float* base = enc + b * HID + h;
    float acc[8];
#pragma unroll
    for (int u = 0; u < 8; ++u) acc[u] = 0.0f;
    for (int t = 0; t < TSTEPS; t += 8) {
#pragma unroll
        for (int u = 0; u < 8; ++u)
            acc[u] = fmaf(aw[t + u], base[(t + u) * (BATCH * HID)], acc[u]);
    }
    float s = ((acc[0] + acc[1]) + (acc[2] + acc[3])) + ((acc[4] + acc[5]) + (acc[6] + acc[7]));
    ctx[b * HID + h] = s;
}

// ---------------- argmax-embed + context@W_cs -> in_dec[b, 300] ----------------
__global__ void indec_kernel(const float* __restrict__ in_char,
                             const float* __restrict__ emb,
                             const float* __restrict__ Wcs,
                             const float* __restrict__ bcs)
{
    __shared__ float ctx_s[HID];
    __shared__ int   top_s;
    const int b = blockIdx.x, tid = threadIdx.x;

    for (int i = tid; i < HID; i += 256) ctx_s[i] = g_ctx[b * HID + i];

    if (tid < 32) {
        float bv = -1e30f; int bi = 0;
        for (int i = tid; i < VOCAB; i += 32) {
            float v = in_char[b * VOCAB + i];
            if (v > bv) { bv = v; bi = i; }
        }
        for (int o = 16; o; o >>= 1) {
            float ov = __shfl_xor_sync(0xffffffffu, bv, o);
            int   oi = __shfl_xor_sync(0xffffffffu, bi, o);
            if (ov > bv || (ov == bv && oi < bi)) { bv = ov; bi = oi; }
        }
        if (tid == 0) top_s = bi;
    }
    __syncthreads();

    if (tid < EMBED) g_indec[b * INDEC + tid] = emb[top_s * EMBED + tid];

    if (tid < 250) {
        float acc = bcs[tid];
        for (int k = 0; k < HID; k += 4) {
            float4 c4 = *(const float4*)&ctx_s[k];
            acc = fmaf(c4.x, Wcs[(k + 0) * 250 + tid], acc);
            acc = fmaf(c4.y, Wcs[(k + 1) * 250 + tid], acc);
            acc = fmaf(c4.z, Wcs[(k + 2) * 250 + tid], acc);
            acc = fmaf(c4.w, Wcs[(k + 3) * 250 + tid], acc);
        }
        g_indec[b * INDEC + EMBED + tid] = acc;
    }
}

// ---------------- GRU gates -> new_h ----------------
__global__ void gru_gates(const float* __restrict__ hidden, float* __restrict__ newh)
{
    const int b = blockIdx.x, n = threadIdx.x;  // 512 threads
    const float* gi = g_gi + b * GATE3;
    const float* gh = g_gh + b * GATE3;
    float r  = fast_sigmoid(gi[n]        + gh[n]);
    float z  = fast_sigmoid(gi[HID + n]  + gh[HID + n]);
    float nn = fast_tanh(gi[2 * HID + n] + r * gh[2 * HID + n]);
    float h  = hidden[b * HID + n];
    newh[b * HID + n] = (1.0f - z) * nn + z * h;
}

// ---------------- output = softmax(new_h @ W_out + b_out) ----------------
__global__ void out_softmax(const float* __restrict__ newh,
                            const float* __restrict__ Wout,
                            const float* __restrict__ bout,
                            float* __restrict__ out)
{
    __shared__ float nh[HID];
    __shared__ float sc[VOCAB];
    __shared__ float red[2];
    const int b = blockIdx.x, tid = threadIdx.x;  // 128 threads

    for (int i = tid; i < HID; i += 128) nh[i] = newh[b * HID + i];
    __syncthreads();

    if (tid < VOCAB) {
        float acc = bout[tid];
        for (int k = 0; k < HID; ++k) acc = fmaf(nh[k], Wout[k * VOCAB + tid], acc);
        sc[tid] = acc;
    }
    __syncthreads();

    if (tid < 32) {
        float mx = -1e30f;
        for (int i = tid; i < VOCAB; i += 32) mx = fmaxf(mx, sc[i]);
        for (int o = 16; o; o >>= 1) mx = fmaxf(mx, __shfl_xor_sync(0xffffffffu, mx, o));
        float sum = 0.0f;
        for (int i = tid; i < VOCAB; i += 32) sum += __expf(sc[i] - mx);
        for (int o = 16; o; o >>= 1) sum += __shfl_xor_sync(0xffffffffu, sum, o);
        if (tid == 0) { red[0] = mx; red[1] = sum; }
    }
    __syncthreads();

    if (tid < VOCAB)
        out[b * VOCAB + tid] = __expf(sc[tid] - red[0]) * (1.0f / red[1]);
}

// ---------------- launch ----------------
extern "C" void kernel_launch(void* const* d_in, const int* in_sizes, int n_in,
                              void* d_out, int out_size)
{
    const float* in_char = (const float*)d_in[0];
    const float* hidden  = (const float*)d_in[1];
    const float* enc     = (const float*)d_in[2];
    const float* W_hp    = (const float*)d_in[3];
    const float* b_hp    = (const float*)d_in[4];
    const float* W_ep    = (const float*)d_in[5];
    const float* b_ep    = (const float*)d_in[6];
    const float* w_v     = (const float*)d_in[7];
    /* d_in[8] = b_v: constant shift under softmax, mathematically irrelevant */
    const float* W_cs    = (const float*)d_in[9];
    const float* b_cs    = (const float*)d_in[10];
    const float* emb     = (const float*)d_in[11];
    const float* W_ih    = (const float*)d_in[12];
    const float* b_ih    = (const float*)d_in[13];
    const float* W_hh    = (const float*)d_in[14];
    const float* b_hh    = (const float*)d_in[15];
    const float* W_out   = (const float*)d_in[16];
    const float* b_out   = (const float*)d_in[17];

    float* out       = (float*)d_out;
    float* out_probs = out;                                  // [256,83]
    float* out_newh  = out + BATCH * VOCAB;                  // [1,256,512]
    float* out_attn  = out + BATCH * VOCAB + BATCH * HID;    // [256,600]

    void *p_ha, *p_scores, *p_ctx, *p_indec, *p_gi, *p_gh;
    cudaGetSymbolAddress(&p_ha,     g_ha);
    cudaGetSymbolAddress(&p_scores, g_scores);
    cudaGetSymbolAddress(&p_ctx,    g_ctx);
    cudaGetSymbolAddress(&p_indec,  g_indec);
    cudaGetSymbolAddress(&p_gi,     g_gi);
    cudaGetSymbolAddress(&p_gh,     g_gh);

    // 1. hidden_attn = hidden @ W_hp + b_hp + b_ep  (b_ep folded in)
    gemm16<<<dim3(HID / 128, BATCH / 16), 128>>>(hidden, W_hp, b_hp, b_ep,
                                                 (float*)p_ha, HID, HID);
    // 2. fused big GEMM (FFMA2) + tanh + w_v reduction -> scores
    attn_scores_kernel<<<MROWS / 128, 256>>>(enc, W_ep, w_v, (float*)p_scores);
    // 3. softmax over T -> attention weights (output #3)
    softmax_T<<<BATCH, 256>>>((const float*)p_scores, out_attn);
    // 4. context = attn-weighted sum of encoder
    context_kernel<<<dim3(HID / 128, BATCH), 128>>>(enc, out_attn, (float*)p_ctx);
    // 5. argmax-embed + context@W_cs -> in_dec
    indec_kernel<<<BATCH, 256>>>(in_char, emb, W_cs, b_cs);
    // 6. gi = in_dec @ W_ih + b_ih
    gemm16<<<dim3(GATE3 / 128, BATCH / 16), 128>>>((const float*)p_indec, W_ih, b_ih,
                                                   nullptr, (float*)p_gi, INDEC, GATE3);
    // 7. gh = h @ W_hh + b_hh
    gemm16<<<dim3(GATE3 / 128, BATCH / 16), 128>>>(hidden, W_hh, b_hh,
                                                   nullptr, (float*)p_gh, HID, GATE3);
    // 8. GRU gates -> new_h (output #2)
    gru_gates<<<BATCH, HID>>>(hidden, out_newh);
    // 9. output probabilities (output #1)
    out_softmax<<<BATCH, 128>>>(out_newh, W_out, b_out, out_probs);
}

// round 5
// speedup vs baseline: 1.8081x; 1.6373x over previous
#include <cuda_runtime.h>
#include <cstdint>

// ---------------- constants ----------------
#define BATCH   256
#define TSTEPS  600
#define HID     512
#define EMBED   50
#define VOCAB   83
#define MROWS   (TSTEPS*BATCH)      // 153600
#define GATE3   (3*HID)             // 1536
#define INDEC   (6*EMBED)           // 300

// ---------------- scratch (__device__ globals; no allocation allowed) ----------------
__device__ float g_ha[BATCH*HID];        // hidden@W_hp + b_hp + b_ep
__device__ float g_scores[BATCH*TSTEPS]; // pre-softmax scores [b*600+t]
__device__ float g_ctx[BATCH*HID];       // attention context
__device__ float g_indec[BATCH*INDEC];   // [embed(50) | context@W_cs (250)]
__device__ float g_gi[BATCH*GATE3];
__device__ float g_gh[BATCH*GATE3];
__device__ float g_Wt[HID*HID];          // W_ep transposed, tf32-rounded: Wt[n][k]

// ---------------- MUFU-free fast math ----------------
__device__ __forceinline__ float fexp2_nomufu(float u) {
    float k = u + 12582912.0f;                       // round-to-nearest int
    int   n = __float_as_int(k) - 0x4B400000;        // integer part
    float f = u - (k - 12582912.0f);                 // f in [-0.5, 0.5]
    float p = 0.0013333558f;
    p = fmaf(p, f, 0.0096181291f);
    p = fmaf(p, f, 0.0555041087f);
    p = fmaf(p, f, 0.2402265069f);
    p = fmaf(p, f, 0.6931471806f);
    p = fmaf(p, f, 1.0f);
    return __int_as_float(__float_as_int(p) + (n << 23));
}

// tanh(x) = 1 - 2/(exp(2x)+1), reciprocal via magic + 3 Newton steps (no MUFU).
__device__ __forceinline__ float fast_tanh(float x) {
    float u = fminf(fmaxf(x * 2.8853900818f, -30.0f), 30.0f);  // 2x*log2(e)
    float e = fexp2_nomufu(u);                                  // exp(2x)
    float d = e + 1.0f;
    float y = __int_as_float(0x7EF311C3 - __float_as_int(d));   // ~1/d guess
    y = y * fmaf(-d, y, 2.0f);
    y = y * fmaf(-d, y, 2.0f);
    y = y * fmaf(-d, y, 2.0f);
    return fmaf(-2.0f, y, 1.0f);
}

__device__ __forceinline__ float fast_sigmoid(float x) {
    return fmaf(0.5f, fast_tanh(0.5f * x), 0.5f);
}

// ---------------- TF32 helpers ----------------
__device__ __forceinline__ float cvt_tf32(float x) {
    float r;
    asm("cvt.rna.tf32.f32 %0, %1;" : "=f"(r) : "f"(x));
    return r;
}
__device__ __forceinline__ void mma_tf32(float* c, const uint32_t* a, const uint32_t* b) {
    asm("mma.sync.aligned.m16n8k8.row.col.f32.tf32.tf32.f32 "
        "{%0,%1,%2,%3}, {%4,%5,%6,%7}, {%8,%9}, {%0,%1,%2,%3};"
        : "+f"(c[0]), "+f"(c[1]), "+f"(c[2]), "+f"(c[3])
        : "r"(a[0]), "r"(a[1]), "r"(a[2]), "r"(a[3]), "r"(b[0]), "r"(b[1]));
}

// ---------------- transpose + tf32-round W_ep -> Wt[n][k] ----------------
__global__ void transpose_cvt(const float* __restrict__ W, float* __restrict__ Wt)
{
    __shared__ float t[32][33];
    const int bx = blockIdx.x * 32, by = blockIdx.y * 32;
    for (int i = threadIdx.y; i < 32; i += 8)
        t[i][threadIdx.x] = W[(by + i) * HID + bx + threadIdx.x];
    __syncthreads();
    for (int i = threadIdx.y; i < 32; i += 8)
        Wt[(bx + i) * HID + by + threadIdx.x] = cvt_tf32(t[threadIdx.x][i]);
}

// ---------------- generic small GEMM: C[256,N] = A[256,K] @ W[K,N] + b1 (+ b2) ----------------
__global__ void gemm16(const float* __restrict__ A, const float* __restrict__ W,
                       const float* __restrict__ b1, const float* __restrict__ b2,
                       float* __restrict__ C, int K, int N)
{
    __shared__ float hs[16][HID];
    const int n  = blockIdx.x * 128 + threadIdx.x;
    const int b0 = blockIdx.y * 16;

    for (int idx = threadIdx.x; idx < 16 * K; idx += 128) {
        int r = idx / K, c = idx - r * K;
        hs[r][c] = A[(b0 + r) * K + c];
    }
    __syncthreads();

    float acc[16];
#pragma unroll
    for (int r = 0; r < 16; ++r) acc[r] = 0.0f;

    for (int k = 0; k < K; k += 4) {
        float w0 = W[(k + 0) * N + n];
        float w1 = W[(k + 1) * N + n];
        float w2 = W[(k + 2) * N + n];
        float w3 = W[(k + 3) * N + n];
#pragma unroll
        for (int r = 0; r < 16; ++r) {
            float4 h4 = *(const float4*)&hs[r][k];
            acc[r] = fmaf(h4.x, w0, acc[r]);
            acc[r] = fmaf(h4.y, w1, acc[r]);
            acc[r] = fmaf(h4.z, w2, acc[r]);
            acc[r] = fmaf(h4.w, w3, acc[r]);
        }
    }
    float bias = b1[n] + (b2 ? b2[n] : 0.0f);
#pragma unroll
    for (int r = 0; r < 16; ++r)
        C[(b0 + r) * N + n] = acc[r] + bias;
}

// ---------------- big fused kernel (TF32 tensor cores) ----------------
// scores[b,t] = w_v . tanh(enc_row @ W_ep + ha[b,:])
// CTA: 256 M-rows, 512 threads (16 warps). Warp tile 32(M)x64(N).
// N looped in 4 chunks of 128; K tiled at 32, smem staged in mma-fragment order.
__global__ __launch_bounds__(512, 1)
void attn_scores_tc(const float* __restrict__ enc,
                    const float* __restrict__ Wt,
                    const float* __restrict__ wv,
                    float* __restrict__ scores)
{
    // A frags: [group 0..15][kstep 0..3][lane 0..31][4]  (group = 16 rows)
    __shared__ float sA[16 * 4 * 32 * 4];   // 32 KB
    // B frags: [ntile 0..15][kstep 0..3][lane 0..31][2]  (ntile = 8 cols)
    __shared__ float sB[16 * 4 * 32 * 2];   // 16 KB

    const int tid  = threadIdx.x;
    const int lane = tid & 31;
    const int wid  = tid >> 5;
    const int wm   = wid >> 1;              // 0..7 : 32-row group
    const int wn   = wid & 1;               // 0..1 : 64-col half
    const int m0   = blockIdx.x * 256;

    float rs[4] = {0.f, 0.f, 0.f, 0.f};     // per-thread row-sum accumulators

    for (int nc = 0; nc < 4; ++nc) {
        float acc[2][8][4];
#pragma unroll
        for (int h = 0; h < 2; ++h)
#pragma unroll
            for (int j = 0; j < 8; ++j)
#pragma unroll
                for (int e = 0; e < 4; ++e) acc[h][j][e] = 0.0f;

        for (int k0 = 0; k0 < HID; k0 += 32) {
            // ---- stage A (256 x 32, tf32-rounded) into fragment order ----
#pragma unroll
            for (int it = 0; it < 4; ++it) {
                int v  = it * 512 + tid;        // 0..2047 float4 slots
                int r  = v >> 3;                // row 0..255
                int c4 = (v & 7) * 4;           // col 0..28
                float4 q = *(const float4*)(enc + (size_t)(m0 + r) * HID + k0 + c4);
                float vals[4] = {q.x, q.y, q.z, q.w};
                int g = r >> 4, rr = r & 15;
#pragma unroll
                for (int e = 0; e < 4; ++e) {
                    int k = c4 + e;
                    int s = k >> 3, kk = k & 7;
                    int ln   = ((rr & 7) << 2) | (kk & 3);
                    int slot = ((rr >> 3) & 1) | (((kk >> 2) & 1) << 1);
                    sA[(((g << 2) + s) * 32 + ln) * 4 + slot] = cvt_tf32(vals[e]);
                }
            }
            // ---- stage B (128 x 32 of Wt chunk; already tf32) ----
#pragma unroll
            for (int it = 0; it < 2; ++it) {
                int v  = it * 512 + tid;        // 0..1023
                int nl = v >> 3;                // 0..127
                int c4 = (v & 7) * 4;
                float4 q = *(const float4*)(Wt + (size_t)(nc * 128 + nl) * HID + k0 + c4);
                float vals[4] = {q.x, q.y, q.z, q.w};
                int j = nl >> 3, nn = nl & 7;
#pragma unroll
                for (int e = 0; e < 4; ++e) {
                    int k = c4 + e;
                    int s = k >> 3, kk = k & 7;
                    int ln   = (nn << 2) | (kk & 3);
                    int slot = (kk >> 2) & 1;
                    sB[(((j << 2) + s) * 32 + ln) * 2 + slot] = vals[e];
                }
            }
            __syncthreads();

            // ---- compute: 4 k-steps of 8 ----
#pragma unroll
            for (int s = 0; s < 4; ++s) {
                uint32_t a0[4], a1[4];
                {
                    int g0 = wm * 2, g1 = g0 + 1;
                    float4 fa0 = *(const float4*)&sA[(((g0 << 2) + s) * 32 + lane) * 4];
                    float4 fa1 = *(const float4*)&sA[(((g1 << 2) + s) * 32 + lane) * 4];
                    a0[0] = __float_as_uint(fa0.x); a0[1] = __float_as_uint(fa0.y);
                    a0[2] = __float_as_uint(fa0.z); a0[3] = __float_as_uint(fa0.w);
                    a1[0] = __float_as_uint(fa1.x); a1[1] = __float_as_uint(fa1.y);
                    a1[2] = __float_as_uint(fa1.z); a1[3] = __float_as_uint(fa1.w);
                }
#pragma unroll
                for (int j8 = 0; j8 < 8; ++j8) {
                    int j = wn * 8 + j8;
                    float2 fb = *(const float2*)&sB[(((j << 2) + s) * 32 + lane) * 2];
                    uint32_t b[2] = {__float_as_uint(fb.x), __float_as_uint(fb.y)};
                    mma_tf32(acc[0][j8], a0, b);
                    mma_tf32(acc[1][j8], a1, b);
                }
            }
            __syncthreads();
        }

        // ---- fused epilogue for this 128-col chunk ----
#pragma unroll
        for (int h = 0; h < 2; ++h) {
            float p0 = 0.0f, p1 = 0.0f;
            const int lrA = wm * 32 + h * 16 + (lane >> 2);   // ha row = local row
#pragma unroll
            for (int j8 = 0; j8 < 8; ++j8) {
                int col0 = nc * 128 + wn * 64 + j8 * 8 + (lane & 3) * 2;
                float2 wvv = *(const float2*)(wv + col0);
                float2 hA  = *(const float2*)(g_ha + lrA * HID + col0);
                float2 hB  = *(const float2*)(g_ha + (lrA + 8) * HID + col0);
                p0 += wvv.x * fast_tanh(acc[h][j8][0] + hA.x)
                    + wvv.y * fast_tanh(acc[h][j8][1] + hA.y);
                p1 += wvv.x * fast_tanh(acc[h][j8][2] + hB.x)
                    + wvv.y * fast_tanh(acc[h][j8][3] + hB.y);
            }
            p0 += __shfl_xor_sync(0xffffffffu, p0, 1);
            p0 += __shfl_xor_sync(0xffffffffu, p0, 2);
            p1 += __shfl_xor_sync(0xffffffffu, p1, 1);
            p1 += __shfl_xor_sync(0xffffffffu, p1, 2);
            rs[h * 2 + 0] += p0;
            rs[h * 2 + 1] += p1;
        }
    }

    // ---- cross-warp (wn halves) combine via smem (reuse sA) ----
    __syncthreads();
    if (tid < 256) sA[tid] = 0.0f;
    __syncthreads();
    if ((lane & 3) == 0) {
        int q = lane >> 2;
#pragma unroll
        for (int rv = 0; rv < 4; ++rv) {
            int lr = wm * 32 + (rv >> 1) * 16 + (rv & 1) * 8 + q;
            atomicAdd(&sA[lr], rs[rv]);
        }
    }
    __syncthreads();
    if (tid < 256) {
        // m = blk*256 + tid ; b = tid, t = blk
        scores[tid * TSTEPS + blockIdx.x] = sA[tid];
    }
}

// ---------------- softmax over T per batch row ----------------
__global__ void softmax_T(const float* __restrict__ scores, float* __restrict__ attn)
{
    __shared__ float red[256];
    const int b = blockIdx.x, tid = threadIdx.x;
    const float* s = scores + b * TSTEPS;

    float mx = -1e30f;
    for (int t = tid; t < TSTEPS; t += 256) mx = fmaxf(mx, s[t]);
    red[tid] = mx; __syncthreads();
    for (int o = 128; o; o >>= 1) { if (tid < o) red[tid] = fmaxf(red[tid], red[tid + o]); __syncthreads(); }
    mx = red[0]; __syncthreads();

    float sum = 0.0f;
    for (int t = tid; t < TSTEPS; t += 256) sum += __expf(s[t] - mx);
    red[tid] = sum; __syncthreads();
    for (int o = 128; o; o >>= 1) { if (tid < o) red[tid] += red[tid + o]; __syncthreads(); }
    const float inv = 1.0f / red[0];

    for (int t = tid; t < TSTEPS; t += 256)
        attn[b * TSTEPS + t] = __expf(s[t] - mx) * inv;
}

// ---------------- context[b,h] = sum_t attn[b,t] * enc[t,b,h] ----------------
__global__ void context_kernel(const float* __restrict__ enc,
                               const float* __restrict__ attn,
                               float* __restrict__ ctx)
{
    __shared__ float aw[TSTEPS];
    const int b = blockIdx.y;
    const int h = blockIdx.x * 128 + threadIdx.x;
    for (int t = threadIdx.x; t < TSTEPS; t += 128) aw[t] = attn[b * TSTEPS + t];
    __syncthreads();

    const float* base = enc + b * HID + h;
    float acc[8];
#pragma unroll
    for (int u = 0; u < 8; ++u) acc[u] = 0.0f;
    for (int t = 0; t < TSTEPS; t += 8) {
#pragma unroll
        for (int u = 0; u < 8; ++u)
            acc[u] = fmaf(aw[t + u], base[(t + u) * (BATCH * HID)], acc[u]);
    }
    float s = ((acc[0] + acc[1]) + (acc[2] + acc[3])) + ((acc[4] + acc[5]) + (acc[6] + acc[7]));
    ctx[b * HID + h] = s;
}

// ---------------- argmax-embed + context@W_cs -> in_dec[b, 300] ----------------
__global__ void indec_kernel(const float* __restrict__ in_char,
                             const float* __restrict__ emb,
                             const float* __restrict__ Wcs,
                             const float* __restrict__ bcs)
{
    __shared__ float ctx_s[HID];
    __shared__ int   top_s;
    const int b = blockIdx.x, tid = threadIdx.x;

    for (int i = tid; i < HID; i += 256) ctx_s[i] = g_ctx[b * HID + i];

    if (tid < 32) {
        float bv = -1e30f; int bi = 0;
        for (int i = tid; i < VOCAB; i += 32) {
            float v = in_char[b * VOCAB + i];
            if (v > bv) { bv = v; bi = i; }
        }
        for (int o = 16; o; o >>= 1) {
            float ov = __shfl_xor_sync(0xffffffffu, bv, o);
            int   oi = __shfl_xor_sync(0xffffffffu, bi, o);
            if (ov > bv || (ov == bv && oi < bi)) { bv = ov; bi = oi; }
        }
        if (tid == 0) top_s = bi;
    }
    __syncthreads();

    if (tid < EMBED) g_indec[b * INDEC + tid] = emb[top_s * EMBED + tid];

    if (tid < 250) {
        float acc = bcs[tid];
        for (int k = 0; k < HID; k += 4) {
            float4 c4 = *(const float4*)&ctx_s[k];
            acc = fmaf(c4.x, Wcs[(k + 0) * 250 + tid], acc);
            acc = fmaf(c4.y, Wcs[(k + 1) * 250 + tid], acc);
            acc = fmaf(c4.z, Wcs[(k + 2) * 250 + tid], acc);
            acc = fmaf(c4.w, Wcs[(k + 3) * 250 + tid], acc);
        }
        g_indec[b * INDEC + EMBED + tid] = acc;
    }
}

// ---------------- GRU gates -> new_h ----------------
__global__ void gru_gates(const float* __restrict__ hidden, float* __restrict__ newh)
{
    const int b = blockIdx.x, n = threadIdx.x;  // 512 threads
    const float* gi = g_gi + b * GATE3;
    const float* gh = g_gh + b * GATE3;
    float r  = fast_sigmoid(gi[n]        + gh[n]);
    float z  = fast_sigmoid(gi[HID + n]  + gh[HID + n]);
    float nn = fast_tanh(gi[2 * HID + n] + r * gh[2 * HID + n]);
    float h  = hidden[b * HID + n];
    newh[b * HID + n] = (1.0f - z) * nn + z * h;
}

// ---------------- output = softmax(new_h @ W_out + b_out) ----------------
__global__ void out_softmax(const float* __restrict__ newh,
                            const float* __restrict__ Wout,
                            const float* __restrict__ bout,
                            float* __restrict__ out)
{
    __shared__ float nh[HID];
    __shared__ float sc[VOCAB];
    __shared__ float red[2];
    const int b = blockIdx.x, tid = threadIdx.x;  // 128 threads

    for (int i = tid; i < HID; i += 128) nh[i] = newh[b * HID + i];
    __syncthreads();

    if (tid < VOCAB) {
        float acc = bout[tid];
        for (int k = 0; k < HID; ++k) acc = fmaf(nh[k], Wout[k * VOCAB + tid], acc);
        sc[tid] = acc;
    }
    __syncthreads();

    if (tid < 32) {
        float mx = -1e30f;
        for (int i = tid; i < VOCAB; i += 32) mx = fmaxf(mx, sc[i]);
        for (int o = 16; o; o >>= 1) mx = fmaxf(mx, __shfl_xor_sync(0xffffffffu, mx, o));
        float sum = 0.0f;
        for (int i = tid; i < VOCAB; i += 32) sum += __expf(sc[i] - mx);
        for (int o = 16; o; o >>= 1) sum += __shfl_xor_sync(0xffffffffu, sum, o);
        if (tid == 0) { red[0] = mx; red[1] = sum; }
    }
    __syncthreads();

    if (tid < VOCAB)
        out[b * VOCAB + tid] = __expf(sc[tid] - red[0]) * (1.0f / red[1]);
}

// ---------------- launch ----------------
extern "C" void kernel_launch(void* const* d_in, const int* in_sizes, int n_in,
                              void* d_out, int out_size)
{
    const float* in_char = (const float*)d_in[0];
    const float* hidden  = (const float*)d_in[1];
    const float* enc     = (const float*)d_in[2];
    const float* W_hp    = (const float*)d_in[3];
    const float* b_hp    = (const float*)d_in[4];
    const float* W_ep    = (const float*)d_in[5];
    const float* b_ep    = (const float*)d_in[6];
    const float* w_v     = (const float*)d_in[7];
    /* d_in[8] = b_v: constant shift under softmax, mathematically irrelevant */
    const float* W_cs    = (const float*)d_in[9];
    const float* b_cs    = (const float*)d_in[10];
    const float* emb     = (const float*)d_in[11];
    const float* W_ih    = (const float*)d_in[12];
    const float* b_ih    = (const float*)d_in[13];
    const float* W_hh    = (const float*)d_in[14];
    const float* b_hh    = (const float*)d_in[15];
    const float* W_out   = (const float*)d_in[16];
    const float* b_out   = (const float*)d_in[17];

    float* out       = (float*)d_out;
    float* out_probs = out;                                  // [256,83]
    float* out_newh  = out + BATCH * VOCAB;                  // [1,256,512]
    float* out_attn  = out + BATCH * VOCAB + BATCH * HID;    // [256,600]

    void *p_ha, *p_scores, *p_ctx, *p_indec, *p_gi, *p_gh, *p_wt;
    cudaGetSymbolAddress(&p_ha,     g_ha);
    cudaGetSymbolAddress(&p_scores, g_scores);
    cudaGetSymbolAddress(&p_ctx,    g_ctx);
    cudaGetSymbolAddress(&p_indec,  g_indec);
    cudaGetSymbolAddress(&p_gi,     g_gi);
    cudaGetSymbolAddress(&p_gh,     g_gh);
    cudaGetSymbolAddress(&p_wt,     g_Wt);

    // 0. Wt[n][k] = tf32(W_ep[k][n])
    transpose_cvt<<<dim3(16, 16), dim3(32, 8)>>>(W_ep, (float*)p_wt);
    // 1. hidden_attn = hidden @ W_hp + b_hp + b_ep  (b_ep folded in)
    gemm16<<<dim3(HID / 128, BATCH / 16), 128>>>(hidden, W_hp, b_hp, b_ep,
                                                 (float*)p_ha, HID, HID);
    // 2. TF32 tensor-core GEMM + tanh + w_v reduction -> scores
    attn_scores_tc<<<MROWS / 256, 512>>>(enc, (const float*)p_wt, w_v, (float*)p_scores);
    // 3. softmax over T -> attention weights (output #3)
    softmax_T<<<BATCH, 256>>>((const float*)p_scores, out_attn);
    // 4. context = attn-weighted sum of encoder
    context_kernel<<<dim3(HID / 128, BATCH), 128>>>(enc, out_attn, (float*)p_ctx);
    // 5. argmax-embed + context@W_cs -> in_dec
    indec_kernel<<<BATCH, 256>>>(in_char, emb, W_cs, b_cs);
    // 6. gi = in_dec @ W_ih + b_ih
    gemm16<<<dim3(GATE3 / 128, BATCH / 16), 128>>>((const float*)p_indec, W_ih, b_ih,
                                                   nullptr, (float*)p_gi, INDEC, GATE3);
    // 7. gh = h @ W_hh + b_hh
    gemm16<<<dim3(GATE3 / 128, BATCH / 16), 128>>>(hidden, W_hh, b_hh,
                                                   nullptr, (float*)p_gh, HID, GATE3);
    // 8. GRU gates -> new_h (output #2)
    gru_gates<<<BATCH, HID>>>(hidden, out_newh);
    // 9. output probabilities (output #1)
    out_softmax<<<BATCH, 128>>>(out_newh, W_out, b_out, out_probs);
}

// round 10
// speedup vs baseline: 2.4171x; 1.3369x over previous
#include <cuda_runtime.h>
#include <cstdint>
#include <cstddef>

// ---------------- constants ----------------
#define BATCH   256
#define TSTEPS  600
#define HID     512
#define EMBED   50
#define VOCAB   83
#define MROWS   (TSTEPS*BATCH)      // 153600
#define GATE3   (3*HID)             // 1536
#define INDEC   (6*EMBED)           // 300

// attn kernel smem layout (floats): A tiles padded rows of 36
#define APITCH  36
#define A_FLOATS (256*APITCH)       // 9216 per buffer
#define B_FLOATS (128*APITCH)       // 4608 per buffer
#define OFF_A0  0
#define OFF_A1  (A_FLOATS)
#define OFF_B0  (2*A_FLOATS)
#define OFF_B1  (2*A_FLOATS + B_FLOATS)
#define OFF_RED (2*A_FLOATS + 2*B_FLOATS)
#define SMEM_FLOATS (OFF_RED + 256)
#define SMEM_BYTES  (SMEM_FLOATS * 4)   // 111616

// ---------------- scratch (__device__ globals; no allocation allowed) ----------------
__device__ float g_ha[BATCH*HID];        // hidden@W_hp + b_hp + b_ep
__device__ float g_scores[BATCH*TSTEPS]; // pre-softmax scores [b*600+t]
__device__ float g_ctx[BATCH*HID];       // attention context
__device__ float g_indec[BATCH*INDEC];   // [embed(50) | context@W_cs (250)]
__device__ float g_gi[BATCH*GATE3];
__device__ float g_gh[BATCH*GATE3];
__device__ float g_Wt[HID*HID];          // W_ep transposed, tf32-rounded: Wt[n][k]

// ---------------- fast math ----------------
__device__ __forceinline__ float tanh_mufu(float x) {
    float y;
    asm("tanh.approx.f32 %0, %1;" : "=f"(y) : "f"(x));
    return y;
}

// accurate MUFU-free tanh for the GRU path (outputs checked directly)
__device__ __forceinline__ float fexp2_nomufu(float u) {
    float k = u + 12582912.0f;
    int   n = __float_as_int(k) - 0x4B400000;
    float f = u - (k - 12582912.0f);
    float p = 0.0013333558f;
    p = fmaf(p, f, 0.0096181291f);
    p = fmaf(p, f, 0.0555041087f);
    p = fmaf(p, f, 0.2402265069f);
    p = fmaf(p, f, 0.6931471806f);
    p = fmaf(p, f, 1.0f);
    return __int_as_float(__float_as_int(p) + (n << 23));
}
__device__ __forceinline__ float fast_tanh(float x) {
    float u = fminf(fmaxf(x * 2.8853900818f, -30.0f), 30.0f);
    float e = fexp2_nomufu(u);
    float d = e + 1.0f;
    float y = __int_as_float(0x7EF311C3 - __float_as_int(d));
    y = y * fmaf(-d, y, 2.0f);
    y = y * fmaf(-d, y, 2.0f);
    y = y * fmaf(-d, y, 2.0f);
    return fmaf(-2.0f, y, 1.0f);
}
__device__ __forceinline__ float fast_sigmoid(float x) {
    return fmaf(0.5f, fast_tanh(0.5f * x), 0.5f);
}

// ---------------- TF32 / async helpers ----------------
__device__ __forceinline__ float cvt_tf32(float x) {
    float r;
    asm("cvt.rna.tf32.f32 %0, %1;" : "=f"(r) : "f"(x));
    return r;
}
__device__ __forceinline__ void mma_tf32(float* c, const uint32_t* a, const uint32_t* b) {
    asm("mma.sync.aligned.m16n8k8.row.col.f32.tf32.tf32.f32 "
        "{%0,%1,%2,%3}, {%4,%5,%6,%7}, {%8,%9}, {%0,%1,%2,%3};"
        : "+f"(c[0]), "+f"(c[1]), "+f"(c[2]), "+f"(c[3])
        : "r"(a[0]), "r"(a[1]), "r"(a[2]), "r"(a[3]), "r"(b[0]), "r"(b[1]));
}
__device__ __forceinline__ void cp16(float* s, const float* g) {
    uint32_t sa = (uint32_t)__cvta_generic_to_shared(s);
    asm volatile("cp.async.cg.shared.global [%0], [%1], 16;" :: "r"(sa), "l"(g));
}
__device__ __forceinline__ void cp_commit() {
    asm volatile("cp.async.commit_group;");
}
template<int N> __device__ __forceinline__ void cp_wait() {
    asm volatile("cp.async.wait_group %0;" :: "n"(N));
}

// ---------------- transpose + tf32-round W_ep -> Wt[n][k] ----------------
__global__ void transpose_cvt(const float* __restrict__ W, float* __restrict__ Wt)
{
    __shared__ float t[32][33];
    const int bx = blockIdx.x * 32, by = blockIdx.y * 32;
    for (int i = threadIdx.y; i < 32; i += 8)
        t[i][threadIdx.x] = W[(by + i) * HID + bx + threadIdx.x];
    __syncthreads();
    for (int i = threadIdx.y; i < 32; i += 8)
        Wt[(bx + i) * HID + by + threadIdx.x] = cvt_tf32(t[threadIdx.x][i]);
}

// ---------------- generic small GEMM: C[256,N] = A[256,K] @ W[K,N] + b1 (+ b2) ----------------
__global__ void gemm16(const float* __restrict__ A, const float* __restrict__ W,
                       const float* __restrict__ b1, const float* __restrict__ b2,
                       float* __restrict__ C, int K, int N)
{
    __shared__ float hs[16][HID];
    const int n  = blockIdx.x * 128 + threadIdx.x;
    const int b0 = blockIdx.y * 16;

    for (int idx = threadIdx.x; idx < 16 * K; idx += 128) {
        int r = idx / K, c = idx - r * K;
        hs[r][c] = A[(b0 + r) * K + c];
    }
    __syncthreads();

    float acc[16];
#pragma unroll
    for (int r = 0; r < 16; ++r) acc[r] = 0.0f;

    for (int k = 0; k < K; k += 4) {
        float w0 = W[(k + 0) * N + n];
        float w1 = W[(k + 1) * N + n];
        float w2 = W[(k + 2) * N + n];
        float w3 = W[(k + 3) * N + n];
#pragma unroll
        for (int r = 0; r < 16; ++r) {
            float4 h4 = *(const float4*)&hs[r][k];
            acc[r] = fmaf(h4.x, w0, acc[r]);
            acc[r] = fmaf(h4.y, w1, acc[r]);
            acc[r] = fmaf(h4.z, w2, acc[r]);
            acc[r] = fmaf(h4.w, w3, acc[r]);
        }
    }
    float bias = b1[n] + (b2 ? b2[n] : 0.0f);
#pragma unroll
    for (int r = 0; r < 16; ++r)
        C[(b0 + r) * N + n] = acc[r] + bias;
}

// ---------------- big fused kernel (TF32 tensor cores, cp.async double-buffered) ----------------
// scores[b,t] = w_v . tanh(enc_row @ W_ep + ha[b,:])
// CTA = 256 rows x 512 threads (16 warps; warp tile 32x64). N in 4 chunks of 128.
// K tiled at 32, row-major smem padded to 36 floats (conflict-free fragment LDS).
// A operand: raw fp32 bits -> tf32 truncation in HW. B pre-rounded (rna) in g_Wt.
__global__ __launch_bounds__(512, 1)
void attn_scores_tc(const float* __restrict__ enc,
                    const float* __restrict__ Wt,
                    const float* __restrict__ wv,
                    float* __restrict__ scores)
{
    extern __shared__ float smem[];

    const int tid  = threadIdx.x;
    const int lane = tid & 31;
    const int wid  = tid >> 5;
    const int wm   = wid >> 1;              // 0..7 : 32-row group
    const int wn   = wid & 1;               // 0..1 : 64-col half
    const int m0   = blockIdx.x * 256;

    // stage phase q = nc*16 + kt  (A tile 256x32, B tile 128x32)
    auto stage = [&](int q) {
        const int nc = q >> 4, k0 = (q & 15) * 32;
        float* Ab = smem + ((q & 1) ? OFF_A1 : OFF_A0);
        float* Bb = smem + ((q & 1) ? OFF_B1 : OFF_B0);
#pragma unroll
        for (int it = 0; it < 4; ++it) {
            int v = it * 512 + tid;
            int r = v >> 3, c4 = (v & 7) << 2;
            cp16(Ab + r * APITCH + c4, enc + (size_t)(m0 + r) * HID + k0 + c4);
        }
#pragma unroll
        for (int it = 0; it < 2; ++it) {
            int v = it * 512 + tid;
            int nrow = v >> 3, c4 = (v & 7) << 2;
            cp16(Bb + nrow * APITCH + c4, Wt + (size_t)(nc * 128 + nrow) * HID + k0 + c4);
        }
        cp_commit();
    };

    float rs[4] = {0.f, 0.f, 0.f, 0.f};

    stage(0);

    for (int nc = 0; nc < 4; ++nc) {
        float acc[2][8][4];
#pragma unroll
        for (int h = 0; h < 2; ++h)
#pragma unroll
            for (int j = 0; j < 8; ++j)
#pragma unroll
                for (int e = 0; e < 4; ++e) acc[h][j][e] = 0.0f;

        for (int kt = 0; kt < 16; ++kt) {
            const int q = nc * 16 + kt;
            if (q < 63) { stage(q + 1); cp_wait<1>(); }
            else        {               cp_wait<0>(); }
            __syncthreads();

            const float* Ab = smem + ((q & 1) ? OFF_A1 : OFF_A0);
            const float* Bb = smem + ((q & 1) ? OFF_B1 : OFF_B0);

#pragma unroll
            for (int s = 0; s < 4; ++s) {
                uint32_t a0[4], a1[4];
                {
                    const float* p0 = Ab + (wm * 32 + (lane >> 2)) * APITCH + s * 8 + (lane & 3);
                    const float* p1 = p0 + 16 * APITCH;
                    a0[0] = __float_as_uint(p0[0]);
                    a0[1] = __float_as_uint(p0[8 * APITCH]);
                    a0[2] = __float_as_uint(p0[4]);
                    a0[3] = __float_as_uint(p0[8 * APITCH + 4]);
                    a1[0] = __float_as_uint(p1[0]);
                    a1[1] = __float_as_uint(p1[8 * APITCH]);
                    a1[2] = __float_as_uint(p1[4]);
                    a1[3] = __float_as_uint(p1[8 * APITCH + 4]);
                }
#pragma unroll
                for (int j8 = 0; j8 < 8; ++j8) {
                    const float* pb = Bb + (wn * 64 + j8 * 8 + (lane >> 2)) * APITCH
                                        + s * 8 + (lane & 3);
                    uint32_t b[2] = { __float_as_uint(pb[0]), __float_as_uint(pb[4]) };
                    mma_tf32(acc[0][j8], a0, b);
                    mma_tf32(acc[1][j8], a1, b);
                }
            }

            if (kt == 15) {
                // fused epilogue for this 128-col chunk: + ha -> tanh -> * w_v -> reduce
#pragma unroll
                for (int h = 0; h < 2; ++h) {
                    float p0 = 0.0f, p1 = 0.0f;
                    const int lrA = wm * 32 + h * 16 + (lane >> 2);
#pragma unroll
                    for (int j8 = 0; j8 < 8; ++j8) {
                        int col0 = nc * 128 + wn * 64 + j8 * 8 + (lane & 3) * 2;
                        float2 wvv = *(const float2*)(wv + col0);
                        float2 hA  = *(const float2*)(g_ha + lrA * HID + col0);
                        float2 hB  = *(const float2*)(g_ha + (lrA + 8) * HID + col0);
                        p0 += wvv.x * tanh_mufu(acc[h][j8][0] + hA.x)
                            + wvv.y * tanh_mufu(acc[h][j8][1] + hA.y);
                        p1 += wvv.x * tanh_mufu(acc[h][j8][2] + hB.x)
                            + wvv.y * tanh_mufu(acc[h][j8][3] + hB.y);
                    }
                    p0 += __shfl_xor_sync(0xffffffffu, p0, 1);
                    p0 += __shfl_xor_sync(0xffffffffu, p0, 2);
                    p1 += __shfl_xor_sync(0xffffffffu, p1, 1);
                    p1 += __shfl_xor_sync(0xffffffffu, p1, 2);
                    rs[h * 2 + 0] += p0;
                    rs[h * 2 + 1] += p1;
                }
            }
            __syncthreads();
        }
    }

    // cross-warp (wn halves) combine
    float* red = smem + OFF_RED;
    if (tid < 256) red[tid] = 0.0f;
    __syncthreads();
    if ((lane & 3) == 0) {
        int qd = lane >> 2;
#pragma unroll
        for (int rv = 0; rv < 4; ++rv) {
            int lr = wm * 32 + (rv >> 1) * 16 + (rv & 1) * 8 + qd;
            atomicAdd(&red[lr], rs[rv]);
        }
    }
    __syncthreads();
    if (tid < 256)
        scores[tid * TSTEPS + blockIdx.x] = red[tid];   // b = tid, t = blk
}

// ---------------- softmax over T per batch row ----------------
__global__ void softmax_T(const float* __restrict__ scores, float* __restrict__ attn)
{
    __shared__ float red[256];
    const int b = blockIdx.x, tid = threadIdx.x;
    const float* s = scores + b * TSTEPS;

    float mx = -1e30f;
    for (int t = tid; t < TSTEPS; t += 256) mx = fmaxf(mx, s[t]);
    red[tid] = mx; __syncthreads();
    for (int o = 128; o; o >>= 1) { if (tid < o) red[tid] = fmaxf(red[tid], red[tid + o]); __syncthreads(); }
    mx = red[0]; __syncthreads();

    float sum = 0.0f;
    for (int t = tid; t < TSTEPS; t += 256) sum += __expf(s[t] - mx);
    red[tid] = sum; __syncthreads();
    for (int o = 128; o; o >>= 1) { if (tid < o) red[tid] += red[tid + o]; __syncthreads(); }
    const float inv = 1.0f / red[0];

    for (int t = tid; t < TSTEPS; t += 256)
        attn[b * TSTEPS + t] = __expf(s[t] - mx) * inv;
}

// ---------------- context[b,h] = sum_t attn[b,t] * enc[t,b,h] ----------------
__global__ void context_kernel(const float* __restrict__ enc,
                               const float* __restrict__ attn,
                               float* __restrict__ ctx)
{
    __shared__ float aw[TSTEPS];
    const int b = blockIdx.y;
    const int h = blockIdx.x * 128 + threadIdx.x;
    for (int t = threadIdx.x; t < TSTEPS; t += 128) aw[t] = attn[b * TSTEPS + t];
    __syncthreads();

    const float* base = enc + b * HID + h;
    float acc[8];
#pragma unroll
    for (int u = 0; u < 8; ++u) acc[u] = 0.0f;
    for (int t = 0; t < TSTEPS; t += 8) {
#pragma unroll
        for (int u = 0; u < 8; ++u)
            acc[u] = fmaf(aw[t + u], base[(t + u) * (BATCH * HID)], acc[u]);
    }
    float s = ((acc[0] + acc[1]) + (acc[2] + acc[3])) + ((acc[4] + acc[5]) + (acc[6] + acc[7]));
    ctx[b * HID + h] = s;
}

// ---------------- argmax-embed + context@W_cs -> in_dec[b, 300] ----------------
__global__ void indec_kernel(const float* __restrict__ in_char,
                             const float* __restrict__ emb,
                             const float* __restrict__ Wcs,
                             const float* __restrict__ bcs)
{
    __shared__ float ctx_s[HID];
    __shared__ int   top_s;
    const int b = blockIdx.x, tid = threadIdx.x;

    for (int i = tid; i < HID; i += 256) ctx_s[i] = g_ctx[b * HID + i];

    if (tid < 32) {
        float bv = -1e30f; int bi = 0;
        for (int i = tid; i < VOCAB; i += 32) {
            float v = in_char[b * VOCAB + i];
            if (v > bv) { bv = v; bi = i; }
        }
        for (int o = 16; o; o >>= 1) {
            float ov = __shfl_xor_sync(0xffffffffu, bv, o);
            int   oi = __shfl_xor_sync(0xffffffffu, bi, o);
            if (ov > bv || (ov == bv && oi < bi)) { bv = ov; bi = oi; }
        }
        if (tid == 0) top_s = bi;
    }
    __syncthreads();

    if (tid < EMBED) g_indec[b * INDEC + tid] = emb[top_s * EMBED + tid];

    if (tid < 250) {
        float acc = bcs[tid];
        for (int k = 0; k < HID; k += 4) {
            float4 c4 = *(const float4*)&ctx_s[k];
            acc = fmaf(c4.x, Wcs[(k + 0) * 250 + tid], acc);
            acc = fmaf(c4.y, Wcs[(k + 1) * 250 + tid], acc);
            acc = fmaf(c4.z, Wcs[(k + 2) * 250 + tid], acc);
            acc = fmaf(c4.w, Wcs[(k + 3) * 250 + tid], acc);
        }
        g_indec[b * INDEC + EMBED + tid] = acc;
    }
}

// ---------------- GRU gates -> new_h (accurate tanh path) ----------------
__global__ void gru_gates(const float* __restrict__ hidden, float* __restrict__ newh)
{
    const int b = blockIdx.x, n = threadIdx.x;  // 512 threads
    const float* gi = g_gi + b * GATE3;
    const float* gh = g_gh + b * GATE3;
    float r  = fast_sigmoid(gi[n]        + gh[n]);
    float z  = fast_sigmoid(gi[HID + n]  + gh[HID + n]);
    float nn = fast_tanh(gi[2 * HID + n] + r * gh[2 * HID + n]);
    float h  = hidden[b * HID + n];
    newh[b * HID + n] = (1.0f - z) * nn + z * h;
}

// ---------------- output = softmax(new_h @ W_out + b_out) ----------------
__global__ void out_softmax(const float* __restrict__ newh,
                            const float* __restrict__ Wout,
                            const float* __restrict__ bout,
                            float* __restrict__ out)
{
    __shared__ float nh[HID];
    __shared__ float sc[VOCAB];
    __shared__ float red[2];
    const int b = blockIdx.x, tid = threadIdx.x;  // 128 threads

    for (int i = tid; i < HID; i += 128) nh[i] = newh[b * HID + i];
    __syncthreads();

    if (tid < VOCAB) {
        float acc = bout[tid];
        for (int k = 0; k < HID; ++k) acc = fmaf(nh[k], Wout[k * VOCAB + tid], acc);
        sc[tid] = acc;
    }
    __syncthreads();

    if (tid < 32) {
        float mx = -1e30f;
        for (int i = tid; i < VOCAB; i += 32) mx = fmaxf(mx, sc[i]);
        for (int o = 16; o; o >>= 1) mx = fmaxf(mx, __shfl_xor_sync(0xffffffffu, mx, o));
        float sum = 0.0f;
        for (int i = tid; i < VOCAB; i += 32) sum += __expf(sc[i] - mx);
        for (int o = 16; o; o >>= 1) sum += __shfl_xor_sync(0xffffffffu, sum, o);
        if (tid == 0) { red[0] = mx; red[1] = sum; }
    }
    __syncthreads();

    if (tid < VOCAB)
        out[b * VOCAB + tid] = __expf(sc[tid] - red[0]) * (1.0f / red[1]);
}

// ---------------- launch ----------------
extern "C" void kernel_launch(void* const* d_in, const int* in_sizes, int n_in,
                              void* d_out, int out_size)
{
    const float* in_char = (const float*)d_in[0];
    const float* hidden  = (const float*)d_in[1];
    const float* enc     = (const float*)d_in[2];
    const float* W_hp    = (const float*)d_in[3];
    const float* b_hp    = (const float*)d_in[4];
    const float* W_ep    = (const float*)d_in[5];
    const float* b_ep    = (const float*)d_in[6];
    const float* w_v     = (const float*)d_in[7];
    /* d_in[8] = b_v: constant shift under softmax, mathematically irrelevant */
    const float* W_cs    = (const float*)d_in[9];
    const float* b_cs    = (const float*)d_in[10];
    const float* emb     = (const float*)d_in[11];
    const float* W_ih    = (const float*)d_in[12];
    const float* b_ih    = (const float*)d_in[13];
    const float* W_hh    = (const float*)d_in[14];
    const float* b_hh    = (const float*)d_in[15];
    const float* W_out   = (const float*)d_in[16];
    const float* b_out   = (const float*)d_in[17];

    float* out       = (float*)d_out;
    float* out_probs = out;                                  // [256,83]
    float* out_newh  = out + BATCH * VOCAB;                  // [1,256,512]
    float* out_attn  = out + BATCH * VOCAB + BATCH * HID;    // [256,600]

    void *p_ha, *p_scores, *p_ctx, *p_indec, *p_gi, *p_gh, *p_wt;
    cudaGetSymbolAddress(&p_ha,     g_ha);
    cudaGetSymbolAddress(&p_scores, g_scores);
    cudaGetSymbolAddress(&p_ctx,    g_ctx);
    cudaGetSymbolAddress(&p_indec,  g_indec);
    cudaGetSymbolAddress(&p_gi,     g_gi);
    cudaGetSymbolAddress(&p_gh,     g_gh);
    cudaGetSymbolAddress(&p_wt,     g_Wt);

    static int smem_set = 0;
    if (!smem_set) {
        cudaFuncSetAttribute(attn_scores_tc,
                             cudaFuncAttributeMaxDynamicSharedMemorySize, SMEM_BYTES);
        smem_set = 1;
    }

    // 0. Wt[n][k] = tf32(W_ep[k][n])
    transpose_cvt<<<dim3(16, 16), dim3(32, 8)>>>(W_ep, (float*)p_wt);
    // 1. hidden_attn = hidden @ W_hp + b_hp + b_ep  (b_ep folded in)
    gemm16<<<dim3(HID / 128, BATCH / 16), 128>>>(hidden, W_hp, b_hp, b_ep,
                                                 (float*)p_ha, HID, HID);
    // 2. TF32 tensor-core GEMM (cp.async pipelined) + tanh + w_v reduction -> scores
    attn_scores_tc<<<MROWS / 256, 512, SMEM_BYTES>>>(enc, (const float*)p_wt, w_v,
                                                     (float*)p_scores);
    // 3. softmax over T -> attention weights (output #3)
    softmax_T<<<BATCH, 256>>>((const float*)p_scores, out_attn);
    // 4. context = attn-weighted sum of encoder
    context_kernel<<<dim3(HID / 128, BATCH), 128>>>(enc, out_attn, (float*)p_ctx);
    // 5. argmax-embed + context@W_cs -> in_dec
    indec_kernel<<<BATCH, 256>>>(in_char, emb, W_cs, b_cs);
    // 6. gi = in_dec @ W_ih + b_ih
    gemm16<<<dim3(GATE3 / 128, BATCH / 16), 128>>>((const float*)p_indec, W_ih, b_ih,
                                                   nullptr, (float*)p_gi, INDEC, GATE3);
    // 7. gh = h @ W_hh + b_hh
    gemm16<<<dim3(GATE3 / 128, BATCH / 16), 128>>>(hidden, W_hh, b_hh,
                                                   nullptr, (float*)p_gh, HID, GATE3);
    // 8. GRU gates -> new_h (output #2)
    gru_gates<<<BATCH, HID>>>(hidden, out_newh);
    // 9. output probabilities (output #1)
    out_softmax<<<BATCH, 128>>>(out_newh, W_out, b_out, out_probs);
}

// round 14
// speedup vs baseline: 2.5472x; 1.0538x over previous
#include <cuda_runtime.h>
#include <cstdint>
#include <cstddef>

// ---------------- constants ----------------
#define BATCH   256
#define TSTEPS  600
#define HID     512
#define EMBED   50
#define VOCAB   83
#define MROWS   (TSTEPS*BATCH)      // 153600
#define GATE3   (3*HID)             // 1536
#define INDEC   (6*EMBED)           // 300

// attn kernel smem layout (floats): A tiles padded rows of 36
#define APITCH  36
#define A_FLOATS (256*APITCH)       // 9216 per buffer
#define B_FLOATS (128*APITCH)       // 4608 per buffer
#define OFF_A0  0
#define OFF_A1  (A_FLOATS)
#define OFF_B0  (2*A_FLOATS)
#define OFF_B1  (2*A_FLOATS + B_FLOATS)
#define OFF_RED (2*A_FLOATS + 2*B_FLOATS)
#define SMEM_FLOATS (OFF_RED + 256)
#define SMEM_BYTES  (SMEM_FLOATS * 4)   // 111616

// ---------------- scratch (__device__ globals; no allocation allowed) ----------------
__device__ float g_ha[BATCH*HID];        // hidden@W_hp + b_hp + b_ep
__device__ float g_scores[BATCH*TSTEPS]; // pre-softmax scores [b*600+t]
__device__ float g_ctx[BATCH*HID];       // attention context
__device__ float g_indec[BATCH*INDEC];   // [embed(50) | context@W_cs (250)]
__device__ float g_gi[BATCH*GATE3];
__device__ float g_gh[BATCH*GATE3];
__device__ float g_Wt[HID*HID];          // W_ep transposed, tf32-rounded: Wt[n][k]

// ---------------- fast math ----------------
__device__ __forceinline__ float tanh_mufu(float x) {
    float y;
    asm("tanh.approx.f32 %0, %1;" : "=f"(y) : "f"(x));
    return y;
}

// accurate MUFU-free tanh for the GRU path (outputs checked directly)
__device__ __forceinline__ float fexp2_nomufu(float u) {
    float k = u + 12582912.0f;
    int   n = __float_as_int(k) - 0x4B400000;
    float f = u - (k - 12582912.0f);
    float p = 0.0013333558f;
    p = fmaf(p, f, 0.0096181291f);
    p = fmaf(p, f, 0.0555041087f);
    p = fmaf(p, f, 0.2402265069f);
    p = fmaf(p, f, 0.6931471806f);
    p = fmaf(p, f, 1.0f);
    return __int_as_float(__float_as_int(p) + (n << 23));
}
__device__ __forceinline__ float fast_tanh(float x) {
    float u = fminf(fmaxf(x * 2.8853900818f, -30.0f), 30.0f);
    float e = fexp2_nomufu(u);
    float d = e + 1.0f;
    float y = __int_as_float(0x7EF311C3 - __float_as_int(d));
    y = y * fmaf(-d, y, 2.0f);
    y = y * fmaf(-d, y, 2.0f);
    y = y * fmaf(-d, y, 2.0f);
    return fmaf(-2.0f, y, 1.0f);
}
__device__ __forceinline__ float fast_sigmoid(float x) {
    return fmaf(0.5f, fast_tanh(0.5f * x), 0.5f);
}

// ---------------- TF32 / async / ldmatrix helpers ----------------
__device__ __forceinline__ float cvt_tf32(float x) {
    float r;
    asm("cvt.rna.tf32.f32 %0, %1;" : "=f"(r) : "f"(x));
    return r;
}
__device__ __forceinline__ void mma_tf32(float* c, const uint32_t* a, const uint32_t* b) {
    asm("mma.sync.aligned.m16n8k8.row.col.f32.tf32.tf32.f32 "
        "{%0,%1,%2,%3}, {%4,%5,%6,%7}, {%8,%9}, {%0,%1,%2,%3};"
        : "+f"(c[0]), "+f"(c[1]), "+f"(c[2]), "+f"(c[3])
        : "r"(a[0]), "r"(a[1]), "r"(a[2]), "r"(a[3]), "r"(b[0]), "r"(b[1]));
}
__device__ __forceinline__ void ldsm4(uint32_t* r, const float* p) {
    uint32_t a = (uint32_t)__cvta_generic_to_shared(p);
    asm volatile("ldmatrix.sync.aligned.m8n8.x4.shared.b16 {%0,%1,%2,%3}, [%4];"
        : "=r"(r[0]), "=r"(r[1]), "=r"(r[2]), "=r"(r[3]) : "r"(a));
}
__device__ __forceinline__ void cp16(float* s, const float* g) {
    uint32_t sa = (uint32_t)__cvta_generic_to_shared(s);
    asm volatile("cp.async.cg.shared.global [%0], [%1], 16;" :: "r"(sa), "l"(g));
}
__device__ __forceinline__ void cp_commit() {
    asm volatile("cp.async.commit_group;");
}
template<int N> __device__ __forceinline__ void cp_wait() {
    asm volatile("cp.async.wait_group %0;" :: "n"(N));
}

// ---------------- transpose + tf32-round W_ep -> Wt[n][k] ----------------
__global__ void transpose_cvt(const float* __restrict__ W, float* __restrict__ Wt)
{
    __shared__ float t[32][33];
    const int bx = blockIdx.x * 32, by = blockIdx.y * 32;
    for (int i = threadIdx.y; i < 32; i += 8)
        t[i][threadIdx.x] = W[(by + i) * HID + bx + threadIdx.x];
    __syncthreads();
    for (int i = threadIdx.y; i < 32; i += 8)
        Wt[(bx + i) * HID + by + threadIdx.x] = cvt_tf32(t[threadIdx.x][i]);
}

// ---------------- generic small GEMM: C[256,N] = A[256,K] @ W[K,N] + b1 (+ b2) ----------------
__global__ void gemm16(const float* __restrict__ A, const float* __restrict__ W,
                       const float* __restrict__ b1, const float* __restrict__ b2,
                       float* __restrict__ C, int K, int N)
{
    __shared__ float hs[16][HID];
    const int n  = blockIdx.x * 128 + threadIdx.x;
    const int b0 = blockIdx.y * 16;

    for (int idx = threadIdx.x; idx < 16 * K; idx += 128) {
        int r = idx / K, c = idx - r * K;
        hs[r][c] = A[(b0 + r) * K + c];
    }
    __syncthreads();

    float acc[16];
#pragma unroll
    for (int r = 0; r < 16; ++r) acc[r] = 0.0f;

    for (int k = 0; k < K; k += 4) {
        float w0 = W[(k + 0) * N + n];
        float w1 = W[(k + 1) * N + n];
        float w2 = W[(k + 2) * N + n];
        float w3 = W[(k + 3) * N + n];
#pragma unroll
        for (int r = 0; r < 16; ++r) {
            float4 h4 = *(const float4*)&hs[r][k];
            acc[r] = fmaf(h4.x, w0, acc[r]);
            acc[r] = fmaf(h4.y, w1, acc[r]);
            acc[r] = fmaf(h4.z, w2, acc[r]);
            acc[r] = fmaf(h4.w, w3, acc[r]);
        }
    }
    float bias = b1[n] + (b2 ? b2[n] : 0.0f);
#pragma unroll
    for (int r = 0; r < 16; ++r)
        C[(b0 + r) * N + n] = acc[r] + bias;
}

// ---------------- big fused kernel (TF32 tensor cores, cp.async + ldmatrix) ----------------
// scores[b,t] = w_v . tanh(enc_row @ W_ep + ha[b,:])
// CTA = 256 rows x 512 threads (16 warps; warp tile 32x64). N in 4 chunks of 128.
// K tiled at 32, row-major smem padded to 36 floats (APITCH%32==4 -> LDSM phases
// hit all 32 banks -> conflict-free). Fragments via ldmatrix.x4.
__global__ __launch_bounds__(512, 1)
void attn_scores_tc(const float* __restrict__ enc,
                    const float* __restrict__ Wt,
                    const float* __restrict__ wv,
                    float* __restrict__ scores)
{
    extern __shared__ float smem[];

    const int tid  = threadIdx.x;
    const int lane = tid & 31;
    const int wid  = tid >> 5;
    const int wm   = wid >> 1;              // 0..7 : 32-row group
    const int wn   = wid & 1;               // 0..1 : 64-col half
    const int m0   = blockIdx.x * 256;

    // ldmatrix per-lane address components (row/col select by lane group)
    const int a_row = wm * 32 + ((lane >> 3) & 1) * 8 + (lane & 7);
    const int a_col = ((lane >> 4) & 1) * 4;
    const int b_row = wn * 64 + ((lane >> 4) & 1) * 8 + (lane & 7);
    const int b_col = ((lane >> 3) & 1) * 4;

    // stage phase q = nc*16 + kt  (A tile 256x32, B tile 128x32)
    auto stage = [&](int q) {
        const int nc = q >> 4, k0 = (q & 15) * 32;
        float* Ab = smem + ((q & 1) ? OFF_A1 : OFF_A0);
        float* Bb = smem + ((q & 1) ? OFF_B1 : OFF_B0);
#pragma unroll
        for (int it = 0; it < 4; ++it) {
            int v = it * 512 + tid;
            int r = v >> 3, c4 = (v & 7) << 2;
            cp16(Ab + r * APITCH + c4, enc + (size_t)(m0 + r) * HID + k0 + c4);
        }
#pragma unroll
        for (int it = 0; it < 2; ++it) {
            int v = it * 512 + tid;
            int nrow = v >> 3, c4 = (v & 7) << 2;
            cp16(Bb + nrow * APITCH + c4, Wt + (size_t)(nc * 128 + nrow) * HID + k0 + c4);
        }
        cp_commit();
    };

    float rs[4] = {0.f, 0.f, 0.f, 0.f};

    stage(0);

    for (int nc = 0; nc < 4; ++nc) {
        float acc[2][8][4];
#pragma unroll
        for (int h = 0; h < 2; ++h)
#pragma unroll
            for (int j = 0; j < 8; ++j)
#pragma unroll
                for (int e = 0; e < 4; ++e) acc[h][j][e] = 0.0f;

        for (int kt = 0; kt < 16; ++kt) {
            const int q = nc * 16 + kt;
            if (q < 63) { stage(q + 1); cp_wait<1>(); }
            else        {               cp_wait<0>(); }
            __syncthreads();

            const float* Ab = smem + ((q & 1) ? OFF_A1 : OFF_A0);
            const float* Bb = smem + ((q & 1) ? OFF_B1 : OFF_B0);
            const float* pA0 = Ab + a_row * APITCH + a_col;
            const float* pA1 = pA0 + 16 * APITCH;
            const float* pB0 = Bb + b_row * APITCH + b_col;

#pragma unroll
            for (int s = 0; s < 4; ++s) {
                uint32_t a0[4], a1[4];
                ldsm4(a0, pA0 + s * 8);
                ldsm4(a1, pA1 + s * 8);
#pragma unroll
                for (int jp = 0; jp < 4; ++jp) {
                    uint32_t rb[4];
                    ldsm4(rb, pB0 + jp * 16 * APITCH + s * 8);
                    mma_tf32(acc[0][2 * jp],     a0, rb);
                    mma_tf32(acc[0][2 * jp + 1], a0, rb + 2);
                    mma_tf32(acc[1][2 * jp],     a1, rb);
                    mma_tf32(acc[1][2 * jp + 1], a1, rb + 2);
                }
            }

            if (kt == 15) {
                // fused epilogue for this 128-col chunk: + ha -> tanh -> * w_v -> reduce
#pragma unroll
                for (int h = 0; h < 2; ++h) {
                    float p0 = 0.0f, p1 = 0.0f;
                    const int lrA = wm * 32 + h * 16 + (lane >> 2);
#pragma unroll
                    for (int j8 = 0; j8 < 8; ++j8) {
                        int col0 = nc * 128 + wn * 64 + j8 * 8 + (lane & 3) * 2;
                        float2 wvv = *(const float2*)(wv + col0);
                        float2 hA  = *(const float2*)(g_ha + lrA * HID + col0);
                        float2 hB  = *(const float2*)(g_ha + (lrA + 8) * HID + col0);
                        p0 += wvv.x * tanh_mufu(acc[h][j8][0] + hA.x)
                            + wvv.y * tanh_mufu(acc[h][j8][1] + hA.y);
                        p1 += wvv.x * tanh_mufu(acc[h][j8][2] + hB.x)
                            + wvv.y * tanh_mufu(acc[h][j8][3] + hB.y);
                    }
                    p0 += __shfl_xor_sync(0xffffffffu, p0, 1);
                    p0 += __shfl_xor_sync(0xffffffffu, p0, 2);
                    p1 += __shfl_xor_sync(0xffffffffu, p1, 1);
                    p1 += __shfl_xor_sync(0xffffffffu, p1, 2);
                    rs[h * 2 + 0] += p0;
                    rs[h * 2 + 1] += p1;
                }
            }
            __syncthreads();
        }
    }

    // cross-warp (wn halves) combine
    float* red = smem + OFF_RED;
    if (tid < 256) red[tid] = 0.0f;
    __syncthreads();
    if ((lane & 3) == 0) {
        int qd = lane >> 2;
#pragma unroll
        for (int rv = 0; rv < 4; ++rv) {
            int lr = wm * 32 + (rv >> 1) * 16 + (rv & 1) * 8 + qd;
            atomicAdd(&red[lr], rs[rv]);
        }
    }
    __syncthreads();
    if (tid < 256)
        scores[tid * TSTEPS + blockIdx.x] = red[tid];   // b = tid, t = blk
}

// ---------------- softmax over T per batch row ----------------
__global__ void softmax_T(const float* __restrict__ scores, float* __restrict__ attn)
{
    __shared__ float red[256];
    const int b = blockIdx.x, tid = threadIdx.x;
    const float* s = scores + b * TSTEPS;

    float mx = -1e30f;
    for (int t = tid; t < TSTEPS; t += 256) mx = fmaxf(mx, s[t]);
    red[tid] = mx; __syncthreads();
    for (int o = 128; o; o >>= 1) { if (tid < o) red[tid] = fmaxf(red[tid], red[tid + o]); __syncthreads(); }
    mx = red[0]; __syncthreads();

    float sum = 0.0f;
    for (int t = tid; t < TSTEPS; t += 256) sum += __expf(s[t] - mx);
    red[tid] = sum; __syncthreads();
    for (int o = 128; o; o >>= 1) { if (tid < o) red[tid] += red[tid + o]; __syncthreads(); }
    const float inv = 1.0f / red[0];

    for (int t = tid; t < TSTEPS; t += 256)
        attn[b * TSTEPS + t] = __expf(s[t] - mx) * inv;
}

// ---------------- context[b,h] = sum_t attn[b,t] * enc[t,b,h] ----------------
__global__ void context_kernel(const float* __restrict__ enc,
                               const float* __restrict__ attn,
                               float* __restrict__ ctx)
{
    __shared__ float aw[TSTEPS];
    const int b = blockIdx.y;
    const int h = blockIdx.x * 128 + threadIdx.x;
    for (int t = threadIdx.x; t < TSTEPS; t += 128) aw[t] = attn[b * TSTEPS + t];
    __syncthreads();

    const float* base = enc + b * HID + h;
    float acc[8];
#pragma unroll
    for (int u = 0; u < 8; ++u) acc[u] = 0.0f;
    for (int t = 0; t < TSTEPS; t += 8) {
#pragma unroll
        for (int u = 0; u < 8; ++u)
            acc[u] = fmaf(aw[t + u], base[(t + u) * (BATCH * HID)], acc[u]);
    }
    float s = ((acc[0] + acc[1]) + (acc[2] + acc[3])) + ((acc[4] + acc[5]) + (acc[6] + acc[7]));
    ctx[b * HID + h] = s;
}

// ---------------- argmax-embed + context@W_cs -> in_dec[b, 300] ----------------
__global__ void indec_kernel(const float* __restrict__ in_char,
                             const float* __restrict__ emb,
                             const float* __restrict__ Wcs,
                             const float* __restrict__ bcs)
{
    __shared__ float ctx_s[HID];
    __shared__ int   top_s;
    const int b = blockIdx.x, tid = threadIdx.x;

    for (int i = tid; i < HID; i += 256) ctx_s[i] = g_ctx[b * HID + i];

    if (tid < 32) {
        float bv = -1e30f; int bi = 0;
        for (int i = tid; i < VOCAB; i += 32) {
            float v = in_char[b * VOCAB + i];
            if (v > bv) { bv = v; bi = i; }
        }
        for (int o = 16; o; o >>= 1) {
            float ov = __shfl_xor_sync(0xffffffffu, bv, o);
            int   oi = __shfl_xor_sync(0xffffffffu, bi, o);
            if (ov > bv || (ov == bv && oi < bi)) { bv = ov; bi = oi; }
        }
        if (tid == 0) top_s = bi;
    }
    __syncthreads();

    if (tid < EMBED) g_indec[b * INDEC + tid] = emb[top_s * EMBED + tid];

    if (tid < 250) {
        float acc = bcs[tid];
        for (int k = 0; k < HID; k += 4) {
            float4 c4 = *(const float4*)&ctx_s[k];
            acc = fmaf(c4.x, Wcs[(k + 0) * 250 + tid], acc);
            acc = fmaf(c4.y, Wcs[(k + 1) * 250 + tid], acc);
            acc = fmaf(c4.z, Wcs[(k + 2) * 250 + tid], acc);
            acc = fmaf(c4.w, Wcs[(k + 3) * 250 + tid], acc);
        }
        g_indec[b * INDEC + EMBED + tid] = acc;
    }
}

// ---------------- GRU gates -> new_h (accurate tanh path) ----------------
__global__ void gru_gates(const float* __restrict__ hidden, float* __restrict__ newh)
{
    const int b = blockIdx.x, n = threadIdx.x;  // 512 threads
    const float* gi = g_gi + b * GATE3;
    const float* gh = g_gh + b * GATE3;
    float r  = fast_sigmoid(gi[n]        + gh[n]);
    float z  = fast_sigmoid(gi[HID + n]  + gh[HID + n]);
    float nn = fast_tanh(gi[2 * HID + n] + r * gh[2 * HID + n]);
    float h  = hidden[b * HID + n];
    newh[b * HID + n] = (1.0f - z) * nn + z * h;
}

// ---------------- output = softmax(new_h @ W_out + b_out) ----------------
__global__ void out_softmax(const float* __restrict__ newh,
                            const float* __restrict__ Wout,
                            const float* __restrict__ bout,
                            float* __restrict__ out)
{
    __shared__ float nh[HID];
    __shared__ float sc[VOCAB];
    __shared__ float red[2];
    const int b = blockIdx.x, tid = threadIdx.x;  // 128 threads

    for (int i = tid; i < HID; i += 128) nh[i] = newh[b * HID + i];
    __syncthreads();

    if (tid < VOCAB) {
        float acc = bout[tid];
        for (int k = 0; k < HID; ++k) acc = fmaf(nh[k], Wout[k * VOCAB + tid], acc);
        sc[tid] = acc;
    }
    __syncthreads();

    if (tid < 32) {
        float mx = -1e30f;
        for (int i = tid; i < VOCAB; i += 32) mx = fmaxf(mx, sc[i]);
        for (int o = 16; o; o >>= 1) mx = fmaxf(mx, __shfl_xor_sync(0xffffffffu, mx, o));
        float sum = 0.0f;
        for (int i = tid; i < VOCAB; i += 32) sum += __expf(sc[i] - mx);
        for (int o = 16; o; o >>= 1) sum += __shfl_xor_sync(0xffffffffu, sum, o);
        if (tid == 0) { red[0] = mx; red[1] = sum; }
    }
    __syncthreads();

    if (tid < VOCAB)
        out[b * VOCAB + tid] = __expf(sc[tid] - red[0]) * (1.0f / red[1]);
}

// ---------------- launch ----------------
extern "C" void kernel_launch(void* const* d_in, const int* in_sizes, int n_in,
                              void* d_out, int out_size)
{
    const float* in_char = (const float*)d_in[0];
    const float* hidden  = (const float*)d_in[1];
    const float* enc     = (const float*)d_in[2];
    const float* W_hp    = (const float*)d_in[3];
    const float* b_hp    = (const float*)d_in[4];
    const float* W_ep    = (const float*)d_in[5];
    const float* b_ep    = (const float*)d_in[6];
    const float* w_v     = (const float*)d_in[7];
    /* d_in[8] = b_v: constant shift under softmax, mathematically irrelevant */
    const float* W_cs    = (const float*)d_in[9];
    const float* b_cs    = (const float*)d_in[10];
    const float* emb     = (const float*)d_in[11];
    const float* W_ih    = (const float*)d_in[12];
    const float* b_ih    = (const float*)d_in[13];
    const float* W_hh    = (const float*)d_in[14];
    const float* b_hh    = (const float*)d_in[15];
    const float* W_out   = (const float*)d_in[16];
    const float* b_out   = (const float*)d_in[17];

    float* out       = (float*)d_out;
    float* out_probs = out;                                  // [256,83]
    float* out_newh  = out + BATCH * VOCAB;                  // [1,256,512]
    float* out_attn  = out + BATCH * VOCAB + BATCH * HID;    // [256,600]

    void *p_ha, *p_scores, *p_ctx, *p_indec, *p_gi, *p_gh, *p_wt;
    cudaGetSymbolAddress(&p_ha,     g_ha);
    cudaGetSymbolAddress(&p_scores, g_scores);
    cudaGetSymbolAddress(&p_ctx,    g_ctx);
    cudaGetSymbolAddress(&p_indec,  g_indec);
    cudaGetSymbolAddress(&p_gi,     g_gi);
    cudaGetSymbolAddress(&p_gh,     g_gh);
    cudaGetSymbolAddress(&p_wt,     g_Wt);

    static int smem_set = 0;
    if (!smem_set) {
        cudaFuncSetAttribute(attn_scores_tc,
                             cudaFuncAttributeMaxDynamicSharedMemorySize, SMEM_BYTES);
        smem_set = 1;
    }

    // 0. Wt[n][k] = tf32(W_ep[k][n])
    transpose_cvt<<<dim3(16, 16), dim3(32, 8)>>>(W_ep, (float*)p_wt);
    // 1. hidden_attn = hidden @ W_hp + b_hp + b_ep  (b_ep folded in)
    gemm16<<<dim3(HID / 128, BATCH / 16), 128>>>(hidden, W_hp, b_hp, b_ep,
                                                 (float*)p_ha, HID, HID);
    // 2. TF32 tensor-core GEMM (cp.async + ldmatrix) + tanh + w_v reduction -> scores
    attn_scores_tc<<<MROWS / 256, 512, SMEM_BYTES>>>(enc, (const float*)p_wt, w_v,
                                                     (float*)p_scores);
    // 3. softmax over T -> attention weights (output #3)
    softmax_T<<<BATCH, 256>>>((const float*)p_scores, out_attn);
    // 4. context = attn-weighted sum of encoder
    context_kernel<<<dim3(HID / 128, BATCH), 128>>>(enc, out_attn, (float*)p_ctx);
    // 5. argmax-embed + context@W_cs -> in_dec
    indec_kernel<<<BATCH, 256>>>(in_char, emb, W_cs, b_cs);
    // 6. gi = in_dec @ W_ih + b_ih
    gemm16<<<dim3(GATE3 / 128, BATCH / 16), 128>>>((const float*)p_indec, W_ih, b_ih,
                                                   nullptr, (float*)p_gi, INDEC, GATE3);
    // 7. gh = h @ W_hh + b_hh
    gemm16<<<dim3(GATE3 / 128, BATCH / 16), 128>>>(hidden, W_hh, b_hh,
                                                   nullptr, (float*)p_gh, HID, GATE3);
    // 8. GRU gates -> new_h (output #2)
    gru_gates<<<BATCH, HID>>>(hidden, out_newh);
    // 9. output probabilities (output #1)
    out_softmax<<<BATCH, 128>>>(out_newh, W_out, b_out, out_probs);
}